// round 13
// baseline (speedup 1.0000x reference)
#include <cuda_runtime.h>
#include <cuda_bf16.h>
#include <cstdint>

#define BB 16
#define NN 4096
#define CC 256

using bf16 = __nv_bfloat16;

// ---------------- scratch (device globals; no allocation allowed) ----------
__device__ __align__(16) bf16  g_xhi[(size_t)BB*NN*CC];   // x split, [B][N][C]
__device__ __align__(16) bf16  g_xlo[(size_t)BB*NN*CC];
__device__ __align__(16) bf16  g_xThi[(size_t)BB*CC*NN];  // x^T split, [B][C][N]
__device__ __align__(16) bf16  g_xTlo[(size_t)BB*CC*NN];
__device__ __align__(16) bf16  g_Whi[3*CC*CC];            // Wq, Wv, Wt split
__device__ __align__(16) bf16  g_Wlo[3*CC*CC];
__device__ __align__(16) bf16  g_WvThi[CC*CC];            // Wv^T split  [k][c]
__device__ __align__(16) bf16  g_WvTlo[CC*CC];
__device__ float g_t[(size_t)BB*NN*CC];     // pre-BN t, [B][N][C]
__device__ float g_Gp[(size_t)3*BB*CC*CC];  // split-K partials of G (3 ways)
__device__ __align__(16) bf16  g_Ghi[(size_t)BB*CC*CC];
__device__ __align__(16) bf16  g_Glo[(size_t)BB*CC*CC];
__device__ __align__(16) bf16  g_E1hi[(size_t)BB*CC*CC];
__device__ __align__(16) bf16  g_E1lo[(size_t)BB*CC*CC];
__device__ float g_att[(size_t)BB*CC*CC];
__device__ __align__(16) bf16  g_atthi[(size_t)BB*CC*CC]; // att/colsum split
__device__ __align__(16) bf16  g_attlo[(size_t)BB*CC*CC];
__device__ __align__(16) bf16  g_Mhi[(size_t)BB*CC*CC];   // M split [o][c]
__device__ __align__(16) bf16  g_Mlo[(size_t)BB*CC*CC];
__device__ __align__(16) bf16  g_Fhi[(size_t)BB*CC*CC];   // Weff = Wt - M.Wv split
__device__ __align__(16) bf16  g_Flo[(size_t)BB*CC*CC];
__device__ float g_beff[BB*CC];             // bt - M.bv
__device__ float g_colsum[BB*CC];
__device__ float g_bns[CC];                 // fused BN Σt per channel
__device__ float g_bnq[CC];                 // fused BN Σt² per channel
__device__ float g_scale[CC];
__device__ float g_shift[CC];

// Stage: Ahi(16K) Alo(16K) Bhi(8K) Blo(8K) = 48KB
#define ST_ALO 16384
#define ST_BHI 32768
#define ST_BLO 40960
#define STAGE  49152
#define SDYN2  (2*STAGE)
#define SDYN3  (3*STAGE)

// ---------------- helpers ---------------------------------------------------
__device__ __forceinline__ uint32_t smem_u32(const void* p){
    uint32_t a;
    asm("{ .reg .u64 t; cvta.to.shared.u64 t, %1; cvt.u32.u64 %0, t; }" : "=r"(a) : "l"(p));
    return a;
}
__device__ __forceinline__ uint32_t sw128(uint32_t o){ return o ^ ((o >> 3) & 0x70); }

__device__ __forceinline__ void ldm4(uint32_t* r, uint32_t addr){
    asm volatile("ldmatrix.sync.aligned.m8n8.x4.shared.b16 {%0,%1,%2,%3}, [%4];"
        : "=r"(r[0]), "=r"(r[1]), "=r"(r[2]), "=r"(r[3]) : "r"(addr));
}
__device__ __forceinline__ void mma_bf16(float* c, const uint32_t* a, const uint32_t* b){
    asm volatile("mma.sync.aligned.m16n8k16.row.col.f32.bf16.bf16.f32 "
        "{%0,%1,%2,%3}, {%4,%5,%6,%7}, {%8,%9}, {%0,%1,%2,%3};"
        : "+f"(c[0]), "+f"(c[1]), "+f"(c[2]), "+f"(c[3])
        : "r"(a[0]), "r"(a[1]), "r"(a[2]), "r"(a[3]), "r"(b[0]), "r"(b[1]));
}
__device__ __forceinline__ void cpa16(uint32_t dst, const void* src){
    asm volatile("cp.async.cg.shared.global [%0], [%1], 16;" :: "r"(dst), "l"(src));
}
__device__ __forceinline__ void split_store(bf16* hi, bf16* lo, size_t i, float v){
    bf16 h = __float2bfloat16(v);
    hi[i] = h;
    lo[i] = __float2bfloat16(v - __bfloat162float(h));
}
__device__ __forceinline__ void split_pair(float v0, float v1, uint32_t& hi, uint32_t& lo){
    bf16 h0 = __float2bfloat16(v0), h1 = __float2bfloat16(v1);
    float r0 = v0 - __bfloat162float(h0), r1 = v1 - __bfloat162float(h1);
    __nv_bfloat162 ph; ph.x = h0; ph.y = h1;
    __nv_bfloat162 pl = __floats2bfloat162_rn(r0, r1);
    hi = *(uint32_t*)&ph;
    lo = *(uint32_t*)&pl;
}
__device__ __forceinline__ void cluster_sync_fenced(){
    __threadfence();
    asm volatile("barrier.cluster.arrive.aligned;" ::: "memory");
    asm volatile("barrier.cluster.wait.aligned;" ::: "memory");
}

// ---------------------------------------------------------------------------
// Split-bf16 128(M)x64(N) GEMM building blocks; NS-stage cp.async pipeline.
// ---------------------------------------------------------------------------
__device__ __forceinline__ void ld_chunk(char* smem, int stage, int tid,
        const bf16* __restrict__ Ahi, const bf16* __restrict__ Alo,
        const bf16* __restrict__ Bhi, const bf16* __restrict__ Blo,
        int ldA, int ldB, int c0){
    uint32_t sbase = smem_u32(smem) + stage * STAGE;
    #pragma unroll
    for (int i = 0; i < 4; i++){           // A: 128 rows x 8 segs
        int g = tid + i * 256;
        int row = g >> 3, cg = g & 7;
        uint32_t so = sw128((uint32_t)(row * 128 + cg * 16));
        size_t ga = (size_t)row * ldA + c0 + cg * 8;
        cpa16(sbase + so,          Ahi + ga);
        cpa16(sbase + ST_ALO + so, Alo + ga);
    }
    #pragma unroll
    for (int i = 0; i < 2; i++){           // B: 64 rows x 8 segs
        int g = tid + i * 256;
        int row = g >> 3, cg = g & 7;
        uint32_t so = sw128((uint32_t)(row * 128 + cg * 16));
        size_t gb = (size_t)row * ldB + c0 + cg * 8;
        cpa16(sbase + ST_BHI + so, Bhi + gb);
        cpa16(sbase + ST_BLO + so, Blo + gb);
    }
    asm volatile("cp.async.commit_group;" ::: "memory");
}

__device__ __forceinline__ void compute_chunk(uint32_t sb, int lane,
        int warpM, int warpN, float acc[2][4][4]){
    #pragma unroll
    for (int ks = 0; ks < 4; ks++){
        uint32_t ahi[2][4], alo[2][4];
        #pragma unroll
        for (int mf = 0; mf < 2; mf++){
            int row = warpM * 32 + mf * 16 + (lane & 15);
            uint32_t off = sw128((uint32_t)(row * 128 + ks * 32 + (lane >> 4) * 16));
            ldm4(ahi[mf], sb + off);
            ldm4(alo[mf], sb + ST_ALO + off);
        }
        #pragma unroll
        for (int ng = 0; ng < 2; ng++){
            int rowb = warpN * 32 + ng * 16 + (lane & 15);
            uint32_t off = sw128((uint32_t)(rowb * 128 + ks * 32 + (lane >> 4) * 16));
            uint32_t bh[4], bl[4];
            ldm4(bh, sb + ST_BHI + off);
            ldm4(bl, sb + ST_BLO + off);
            uint32_t bh0[2] = {bh[0], bh[2]}, bh1[2] = {bh[1], bh[3]};
            uint32_t bl0[2] = {bl[0], bl[2]}, bl1[2] = {bl[1], bl[3]};
            #pragma unroll
            for (int mf = 0; mf < 2; mf++){
                mma_bf16(acc[mf][ng*2],     ahi[mf], bh0);
                mma_bf16(acc[mf][ng*2],     ahi[mf], bl0);
                mma_bf16(acc[mf][ng*2],     alo[mf], bh0);
                mma_bf16(acc[mf][ng*2 + 1], ahi[mf], bh1);
                mma_bf16(acc[mf][ng*2 + 1], ahi[mf], bl1);
                mma_bf16(acc[mf][ng*2 + 1], alo[mf], bh1);
            }
        }
    }
}

template<int NS>
__device__ __forceinline__ void gemm_main(char* smem,
        const bf16* __restrict__ Ahi, const bf16* __restrict__ Alo, int ldA,
        const bf16* __restrict__ Bhi, const bf16* __restrict__ Blo, int ldB,
        int nChunks, float acc[2][4][4])
{
    int tid = threadIdx.x, lane = tid & 31, wid = tid >> 5;
    int warpM = wid & 3, warpN = wid >> 2;
    uint32_t sb0 = smem_u32(smem);

    int issued = 0, ldst = 0, cst = 0;
    int npre = (nChunks < NS - 1) ? nChunks : (NS - 1);
    for (int i = 0; i < npre; i++){
        ld_chunk(smem, ldst, tid, Ahi, Alo, Bhi, Blo, ldA, ldB, issued * 64);
        issued++; ldst = (ldst + 1 == NS) ? 0 : ldst + 1;
    }
    for (int cc = 0; cc < nChunks; cc++){
        if (issued < nChunks){
            ld_chunk(smem, ldst, tid, Ahi, Alo, Bhi, Blo, ldA, ldB, issued * 64);
            issued++; ldst = (ldst + 1 == NS) ? 0 : ldst + 1;
        }
        int pend = issued - cc - 1;
        if (pend >= 2)      asm volatile("cp.async.wait_group 2;" ::: "memory");
        else if (pend == 1) asm volatile("cp.async.wait_group 1;" ::: "memory");
        else                asm volatile("cp.async.wait_group 0;" ::: "memory");
        __syncthreads();
        compute_chunk(sb0 + cst * STAGE, lane, warpM, warpN, acc);
        cst = (cst + 1 == NS) ? 0 : cst + 1;
        __syncthreads();
    }
}

// ---------------- conversion: x -> split x AND split x^T --------------------
__global__ void __launch_bounds__(256) k_cvt_x(const float* __restrict__ x){
    int b = blockIdx.z, n0 = blockIdx.x * 64, c0 = blockIdx.y * 64;
    __shared__ float xs[64][65];
    int t = threadIdx.x;
    const float* xb = x + ((size_t)b * NN + n0) * CC + c0;
    #pragma unroll
    for (int p = 0; p < 4; p++){
        int row = p * 16 + (t >> 4);
        int c4  = (t & 15) * 4;
        float4 v = *(const float4*)(xb + (size_t)row * CC + c4);
        uint32_t h0, l0, h1, l1;
        split_pair(v.x, v.y, h0, l0);
        split_pair(v.z, v.w, h1, l1);
        size_t di = ((size_t)b * NN + n0 + row) * CC + c0 + c4;
        *(uint2*)(g_xhi + di) = make_uint2(h0, h1);
        *(uint2*)(g_xlo + di) = make_uint2(l0, l1);
        xs[row][c4 + 0] = v.x; xs[row][c4 + 1] = v.y;
        xs[row][c4 + 2] = v.z; xs[row][c4 + 3] = v.w;
    }
    __syncthreads();
    #pragma unroll
    for (int p = 0; p < 4; p++){
        int cl = p * 16 + (t >> 4);
        int n4 = (t & 15) * 4;
        float v0 = xs[n4][cl], v1 = xs[n4+1][cl], v2 = xs[n4+2][cl], v3 = xs[n4+3][cl];
        uint32_t h0, l0, h1, l1;
        split_pair(v0, v1, h0, l0);
        split_pair(v2, v3, h1, l1);
        size_t di = ((size_t)b * CC + c0 + cl) * NN + n0 + n4;
        *(uint2*)(g_xThi + di) = make_uint2(h0, h1);
        *(uint2*)(g_xTlo + di) = make_uint2(l0, l1);
    }
}
__global__ void k_cvt_w(const float* __restrict__ Wq, const float* __restrict__ Wv,
                        const float* __restrict__ Wt){
    // side duties: zero colsum + BN accumulators (this kernel gates the chain)
    if (blockIdx.x < 16) g_colsum[blockIdx.x * 256 + threadIdx.x] = 0.f;
    if (blockIdx.x == 16){ g_bns[threadIdx.x] = 0.f; g_bnq[threadIdx.x] = 0.f; }
    int idx = blockIdx.x * blockDim.x + threadIdx.x;
    int which = idx >> 16, rem = idx & 65535;
    const float* s = (which == 0) ? Wq : (which == 1) ? Wv : Wt;
    float v = s[rem];
    split_store(g_Whi, g_Wlo, idx, v);
    if (which == 1){
        int o = rem >> 8, c = rem & 255;          // Wv[o][c] -> WvT[c][o]
        split_store(g_WvThi, g_WvTlo, (size_t)c * CC + o, v);
    }
}

// ---------------- KTG: G = x^T x (split-K x3, symmetric: 6 of 8 tiles) ------
__constant__ int c_tileC[6] = {0, 0, 0, 0, 128, 128};
__constant__ int c_tileD[6] = {0, 64, 128, 192, 128, 192};
__constant__ int c_ks0[3] = {0, 22, 43};    // chunk start (64-wide chunks)
__constant__ int c_ksn[3] = {22, 21, 21};   // chunk count
__global__ void __launch_bounds__(256, 1)
ktG(){
    extern __shared__ char smem[];
    int b = blockIdx.z / 3, ks = blockIdx.z % 3;
    int cBase = c_tileC[blockIdx.x], dBase = c_tileD[blockIdx.x];
    size_t kOff = (size_t)c_ks0[ks] * 64;
    int nch = c_ksn[ks];
    const bf16* Ah = g_xThi + ((size_t)b * CC + cBase) * NN + kOff;
    const bf16* Al = g_xTlo + ((size_t)b * CC + cBase) * NN + kOff;
    const bf16* Bh = g_xThi + ((size_t)b * CC + dBase) * NN + kOff;
    const bf16* Bl = g_xTlo + ((size_t)b * CC + dBase) * NN + kOff;
    float acc[2][4][4] = {};
    gemm_main<3>(smem, Ah, Al, NN, Bh, Bl, NN, nch, acc);

    int tid = threadIdx.x, lane = tid & 31, wid = tid >> 5;
    int warpM = wid & 3, warpN = wid >> 2;
    int gr = lane >> 2, gc = (lane & 3) * 2;
    float* dst = g_Gp + ((size_t)(ks * BB + b)) * CC * CC;
    #pragma unroll
    for (int mf = 0; mf < 2; mf++)
        #pragma unroll
        for (int nf = 0; nf < 4; nf++){
            float* c = acc[mf][nf];
            int row0 = warpM * 32 + mf * 16 + gr;
            int col  = warpN * 32 + nf * 8 + gc;
            #pragma unroll
            for (int h = 0; h < 2; h++)
                *(float2*)(dst + (size_t)(cBase + row0 + h*8) * CC + dBase + col)
                    = make_float2(c[2*h], c[2*h+1]);
        }
}

// ---------------- KCHAIN: per-batch attention chain, one 8-CTA cluster ------
// CTA r in cluster: tile mBase=(r>>2)*128, nBase=(r&3)*64.
// Phases: gsum -> E1 -> E -> softmax+colsum -> attS -> M -> Weff+beff.
__global__ void __launch_bounds__(256) __cluster_dims__(8, 1, 1)
kchain(const float* __restrict__ Wt, const float* __restrict__ bt,
       const float* __restrict__ bv){
    extern __shared__ char smem[];
    int r = blockIdx.x, b = blockIdx.y;
    int tid = threadIdx.x, lane = tid & 31, wid = tid >> 5;
    int warpM = wid & 3, warpN = wid >> 2;
    int gr = lane >> 2, gc = (lane & 3) * 2;
    size_t boff = (size_t)b * CC * CC;
    int mBase = (r >> 2) * 128, nBase = (r & 3) * 64;

    // -------- phase 0: gsum for batch b (sum split-K partials + mirror) -----
    {
        const size_t S = (size_t)BB * CC * CC;
        #pragma unroll
        for (int it = 0; it < 8; it++){
            int local = ((it * 8 + r) * 256 + tid) * 4;
            size_t i = boff + (size_t)local;
            int rr = local >> 8, c0 = local & 255;
            float v[4];
            if (rr >= 128 && c0 < 128){
                #pragma unroll
                for (int j = 0; j < 4; j++){
                    size_t src = boff + (size_t)(c0 + j) * CC + rr;
                    v[j] = g_Gp[src] + g_Gp[S + src] + g_Gp[2*S + src];
                }
            } else {
                float4 a  = *(const float4*)(g_Gp + i);
                float4 b2 = *(const float4*)(g_Gp + S + i);
                float4 c2 = *(const float4*)(g_Gp + 2*S + i);
                v[0] = a.x+b2.x+c2.x; v[1] = a.y+b2.y+c2.y;
                v[2] = a.z+b2.z+c2.z; v[3] = a.w+b2.w+c2.w;
            }
            uint32_t h0,l0,h1,l1;
            split_pair(v[0],v[1],h0,l0); split_pair(v[2],v[3],h1,l1);
            *(uint2*)(g_Ghi + i) = make_uint2(h0,h1);
            *(uint2*)(g_Glo + i) = make_uint2(l0,l1);
        }
    }
    cluster_sync_fenced();

    // -------- phase A: E1 = Wq . G ------------------------------------------
    {
        float acc[2][4][4] = {};
        gemm_main<2>(smem, g_Whi + mBase * CC, g_Wlo + mBase * CC, CC,
                     g_Ghi + boff + nBase * CC, g_Glo + boff + nBase * CC, CC, 4, acc);
        #pragma unroll
        for (int mf = 0; mf < 2; mf++)
            #pragma unroll
            for (int nf = 0; nf < 4; nf++){
                float* c = acc[mf][nf];
                int row0 = warpM * 32 + mf * 16 + gr;
                int col  = warpN * 32 + nf * 8 + gc;
                #pragma unroll
                for (int h = 0; h < 2; h++){
                    size_t di = boff + (size_t)(mBase + row0 + h*8) * CC + nBase + col;
                    uint32_t hi, lo;
                    split_pair(c[2*h], c[2*h+1], hi, lo);
                    *(uint32_t*)(g_E1hi + di) = hi;
                    *(uint32_t*)(g_E1lo + di) = lo;
                }
            }
    }
    cluster_sync_fenced();

    // -------- phase B: E = E1 . Wq^T -> fp32 g_att --------------------------
    {
        float acc[2][4][4] = {};
        gemm_main<2>(smem, g_E1hi + boff + mBase * CC, g_E1lo + boff + mBase * CC, CC,
                     g_Whi + nBase * CC, g_Wlo + nBase * CC, CC, 4, acc);
        #pragma unroll
        for (int mf = 0; mf < 2; mf++)
            #pragma unroll
            for (int nf = 0; nf < 4; nf++){
                float* c = acc[mf][nf];
                int row0 = warpM * 32 + mf * 16 + gr;
                int col  = warpN * 32 + nf * 8 + gc;
                #pragma unroll
                for (int h = 0; h < 2; h++){
                    size_t di = boff + (size_t)(mBase + row0 + h*8) * CC + nBase + col;
                    *(float2*)(g_att + di) = make_float2(c[2*h], c[2*h+1]);
                }
            }
    }
    cluster_sync_fenced();

    // -------- phase C: softmax rows [r*32, r*32+32) + colsum atomics --------
    {
        float cs[8] = {0,0,0,0,0,0,0,0};
        int rowBase = r * 32;
        #pragma unroll
        for (int it = 0; it < 4; it++){
            int row = rowBase + wid + it * 8;
            float* p = g_att + boff + (size_t)row * CC;
            float4 a0 = *(float4*)(p + lane * 8);
            float4 a1 = *(float4*)(p + lane * 8 + 4);
            float vv[8] = {a0.x,a0.y,a0.z,a0.w,a1.x,a1.y,a1.z,a1.w};
            float m = vv[0];
            #pragma unroll
            for (int k = 1; k < 8; k++) m = fmaxf(m, vv[k]);
            #pragma unroll
            for (int o = 16; o > 0; o >>= 1) m = fmaxf(m, __shfl_xor_sync(0xffffffffu, m, o));
            float e[8], s = 0.f;
            #pragma unroll
            for (int k = 0; k < 8; k++){ e[k] = __expf(vv[k] - m); s += e[k]; }
            #pragma unroll
            for (int o = 16; o > 0; o >>= 1) s += __shfl_xor_sync(0xffffffffu, s, o);
            float inv = 1.0f / s;
            #pragma unroll
            for (int k = 0; k < 8; k++){ e[k] *= inv; cs[k] += e[k]; }
            *(float4*)(p + lane * 8)     = make_float4(e[0], e[1], e[2], e[3]);
            *(float4*)(p + lane * 8 + 4) = make_float4(e[4], e[5], e[6], e[7]);
        }
        #pragma unroll
        for (int k = 0; k < 8; k++)
            atomicAdd(&g_colsum[b * CC + lane * 8 + k], cs[k]);
    }
    cluster_sync_fenced();

    // -------- phase D: attS = att / (1e-9 + colsum), split ------------------
    {
        #pragma unroll
        for (int it = 0; it < 8; it++){
            int idx = it * 256 + tid;            // 2048 float4 per CTA
            int row = r * 32 + (idx >> 6);
            int col = (idx & 63) * 4;
            size_t i = boff + (size_t)row * CC + col;
            float4 a  = *(const float4*)(g_att + i);
            float4 cv = *(const float4*)(g_colsum + b * CC + col);
            float v0 = a.x / (1e-9f + cv.x), v1 = a.y / (1e-9f + cv.y);
            float v2 = a.z / (1e-9f + cv.z), v3 = a.w / (1e-9f + cv.w);
            uint32_t h0,l0,h1,l1;
            split_pair(v0,v1,h0,l0); split_pair(v2,v3,h1,l1);
            *(uint2*)(g_atthi + i) = make_uint2(h0,h1);
            *(uint2*)(g_attlo + i) = make_uint2(l0,l1);
        }
    }
    cluster_sync_fenced();

    // -------- phase E: M = Wt . attS ----------------------------------------
    {
        float acc[2][4][4] = {};
        gemm_main<2>(smem, g_Whi + 2*CC*CC + mBase * CC, g_Wlo + 2*CC*CC + mBase * CC, CC,
                     g_atthi + boff + nBase * CC, g_attlo + boff + nBase * CC, CC, 4, acc);
        #pragma unroll
        for (int mf = 0; mf < 2; mf++)
            #pragma unroll
            for (int nf = 0; nf < 4; nf++){
                float* c = acc[mf][nf];
                int row0 = warpM * 32 + mf * 16 + gr;
                int col  = warpN * 32 + nf * 8 + gc;
                #pragma unroll
                for (int h = 0; h < 2; h++){
                    size_t di = boff + (size_t)(mBase + row0 + h*8) * CC + nBase + col;
                    uint32_t hi, lo;
                    split_pair(c[2*h], c[2*h+1], hi, lo);
                    *(uint32_t*)(g_Mhi + di) = hi;
                    *(uint32_t*)(g_Mlo + di) = lo;
                }
            }
    }
    cluster_sync_fenced();

    // -------- phase F: Weff = Wt - M.Wv (+ beff on nBase==0 CTAs) -----------
    {
        float acc[2][4][4] = {};
        gemm_main<2>(smem, g_Mhi + boff + mBase * CC, g_Mlo + boff + mBase * CC, CC,
                     g_WvThi + nBase * CC, g_WvTlo + nBase * CC, CC, 4, acc);
        #pragma unroll
        for (int mf = 0; mf < 2; mf++)
            #pragma unroll
            for (int nf = 0; nf < 4; nf++){
                float* c = acc[mf][nf];
                int row0 = warpM * 32 + mf * 16 + gr;
                int col  = warpN * 32 + nf * 8 + gc;
                #pragma unroll
                for (int h = 0; h < 2; h++){
                    int rr = mBase + row0 + h*8, kk = nBase + col;
                    size_t di = boff + (size_t)rr * CC + kk;
                    float w0 = Wt[(size_t)rr * CC + kk];
                    float w1 = Wt[(size_t)rr * CC + kk + 1];
                    uint32_t hi, lo;
                    split_pair(w0 - c[2*h], w1 - c[2*h+1], hi, lo);
                    *(uint32_t*)(g_Fhi + di) = hi;
                    *(uint32_t*)(g_Flo + di) = lo;
                }
            }
        if ((r & 3) == 0 && tid < 128){
            int o = mBase + tid;
            const bf16* mh = g_Mhi + boff + (size_t)o * CC;
            const bf16* ml = g_Mlo + boff + (size_t)o * CC;
            float s = 0.f;
            for (int c = 0; c < CC; c++)
                s += (__bfloat162float(mh[c]) + __bfloat162float(ml[c])) * bv[c];
            g_beff[b * CC + o] = bt[o] - s;
        }
    }
}

// ---------------- KT7: t = x.Weff^T + beff  (K=256) + fused BN sums ---------
__global__ void __launch_bounds__(256, 2)
kt7(){
    extern __shared__ char smem[];
    int b = blockIdx.z;
    int mBase = blockIdx.x * 128;   // n
    int oBase = blockIdx.y * 64;    // o
    const bf16* Ah = g_xhi + ((size_t)b * NN + mBase) * CC;
    const bf16* Al = g_xlo + ((size_t)b * NN + mBase) * CC;
    const bf16* Bh = g_Fhi + ((size_t)b * CC + oBase) * CC;
    const bf16* Bl = g_Flo + ((size_t)b * CC + oBase) * CC;
    float acc[2][4][4] = {};
    gemm_main<2>(smem, Ah, Al, CC, Bh, Bl, CC, 4, acc);

    int tid = threadIdx.x, lane = tid & 31, wid = tid >> 5;
    int warpM = wid & 3, warpN = wid >> 2;

    __shared__ float bn_s[64], bn_q[64];
    if (tid < 64){ bn_s[tid] = 0.f; bn_q[tid] = 0.f; }
    __syncthreads();

    int gr = lane >> 2, gc = (lane & 3) * 2;
    float sA[4][2], qA[4][2];
    #pragma unroll
    for (int nf = 0; nf < 4; nf++){
        sA[nf][0] = sA[nf][1] = qA[nf][0] = qA[nf][1] = 0.f;
        int col = warpN * 32 + nf * 8 + gc;
        int o = oBase + col;
        float b0f = g_beff[b * CC + o], b1f = g_beff[b * CC + o + 1];
        #pragma unroll
        for (int mf = 0; mf < 2; mf++){
            float* c = acc[mf][nf];
            int row0 = warpM * 32 + mf * 16 + gr;
            #pragma unroll
            for (int h = 0; h < 2; h++){
                int n = mBase + row0 + h * 8;
                float v0 = c[2*h] + b0f, v1 = c[2*h+1] + b1f;
                *(float2*)(g_t + ((size_t)b * NN + n) * CC + o) = make_float2(v0, v1);
                sA[nf][0] += v0;       sA[nf][1] += v1;
                qA[nf][0] += v0 * v0;  qA[nf][1] += v1 * v1;
            }
        }
    }
    #pragma unroll
    for (int nf = 0; nf < 4; nf++){
        #pragma unroll
        for (int st = 4; st < 32; st <<= 1){
            sA[nf][0] += __shfl_down_sync(0xffffffffu, sA[nf][0], st);
            sA[nf][1] += __shfl_down_sync(0xffffffffu, sA[nf][1], st);
            qA[nf][0] += __shfl_down_sync(0xffffffffu, qA[nf][0], st);
            qA[nf][1] += __shfl_down_sync(0xffffffffu, qA[nf][1], st);
        }
    }
    if (lane < 4){
        #pragma unroll
        for (int nf = 0; nf < 4; nf++){
            int colL = warpN * 32 + nf * 8 + lane * 2;
            atomicAdd(&bn_s[colL],     sA[nf][0]);
            atomicAdd(&bn_s[colL + 1], sA[nf][1]);
            atomicAdd(&bn_q[colL],     qA[nf][0]);
            atomicAdd(&bn_q[colL + 1], qA[nf][1]);
        }
    }
    __syncthreads();
    if (tid < 64){
        atomicAdd(&g_bns[oBase + tid], bn_s[tid]);
        atomicAdd(&g_bnq[oBase + tid], bn_q[tid]);
    }
}

// ---------------- BN finalize + final --------------------------------------
__global__ void k_bnfin(const float* __restrict__ gamma, const float* __restrict__ beta){
    int o = threadIdx.x;
    float inv = 1.0f / (float)(BB * NN);
    float mean = g_bns[o] * inv;
    float var  = g_bnq[o] * inv - mean * mean;
    float rstd = rsqrtf(var + 1e-5f);
    float sc = gamma[o] * rstd;
    g_scale[o] = sc;
    g_shift[o] = beta[o] - mean * sc;
}
__global__ void k_final(const float* __restrict__ x, float* __restrict__ out){
    size_t i = ((size_t)blockIdx.x * blockDim.x + threadIdx.x) * 4;
    int o = (int)(i & (CC - 1));
    float4 t4 = *(const float4*)(g_t + i);
    float4 x4 = *(const float4*)(x + i);
    float4 sc = *(const float4*)(g_scale + o);
    float4 sh = *(const float4*)(g_shift + o);
    float4 r;
    r.x = x4.x + fmaxf(fmaf(t4.x, sc.x, sh.x), 0.f);
    r.y = x4.y + fmaxf(fmaf(t4.y, sc.y, sh.y), 0.f);
    r.z = x4.z + fmaxf(fmaf(t4.z, sc.z, sh.z), 0.f);
    r.w = x4.w + fmaxf(fmaf(t4.w, sc.w, sh.w), 0.f);
    *(float4*)(out + i) = r;
}

// ---------------- launch ----------------------------------------------------
extern "C" void kernel_launch(void* const* d_in, const int* in_sizes, int n_in,
                              void* d_out, int out_size){
    (void)in_sizes; (void)n_in; (void)out_size;
    const float* x     = (const float*)d_in[1];
    const float* Wq    = (const float*)d_in[2];
    const float* Wv    = (const float*)d_in[3];
    const float* bv    = (const float*)d_in[4];
    const float* Wt    = (const float*)d_in[5];
    const float* bt    = (const float*)d_in[6];
    const float* gamma = (const float*)d_in[7];
    const float* beta  = (const float*)d_in[8];
    float* out = (float*)d_out;

    static bool init_done = false;
    if (!init_done){
        cudaFuncSetAttribute(ktG,    cudaFuncAttributeMaxDynamicSharedMemorySize, SDYN3);
        cudaFuncSetAttribute(kchain, cudaFuncAttributeMaxDynamicSharedMemorySize, SDYN2);
        cudaFuncSetAttribute(kt7,    cudaFuncAttributeMaxDynamicSharedMemorySize, SDYN2);
        init_done = true;
    }

    k_cvt_x <<<dim3(64, 4, BB), 256>>>(x);
    k_cvt_w <<<768, 256>>>(Wq, Wv, Wt);
    ktG     <<<dim3(6, 1, 3*BB), 256, SDYN3>>>();
    kchain  <<<dim3(8, BB), 256, SDYN2>>>(Wt, bt, bv);
    kt7     <<<dim3(32, 4, BB), 256, SDYN2>>>();
    k_bnfin <<<1, 256>>>(gamma, beta);
    k_final <<<16384, 256>>>(x, out);
}

// round 14
// speedup vs baseline: 1.1510x; 1.1510x over previous
#include <cuda_runtime.h>
#include <cuda_bf16.h>
#include <cstdint>

#define BB 16
#define NN 4096
#define CC 256

using bf16 = __nv_bfloat16;

// ---------------- scratch (device globals; no allocation allowed) ----------
__device__ __align__(16) bf16  g_xhi[(size_t)BB*NN*CC];   // x split, [B][N][C]
__device__ __align__(16) bf16  g_xlo[(size_t)BB*NN*CC];
__device__ __align__(16) bf16  g_xThi[(size_t)BB*CC*NN];  // x^T split, [B][C][N]
__device__ __align__(16) bf16  g_xTlo[(size_t)BB*CC*NN];
__device__ __align__(16) bf16  g_Whi[3*CC*CC];            // Wq, Wv, Wt split
__device__ __align__(16) bf16  g_Wlo[3*CC*CC];
__device__ __align__(16) bf16  g_WvThi[CC*CC];            // Wv^T split  [k][c]
__device__ __align__(16) bf16  g_WvTlo[CC*CC];
__device__ float g_Gp[(size_t)3*BB*CC*CC];  // split-K partials of G (3 ways)
__device__ __align__(16) bf16  g_Ghi[(size_t)BB*CC*CC];
__device__ __align__(16) bf16  g_Glo[(size_t)BB*CC*CC];
__device__ __align__(16) bf16  g_E1hi[(size_t)BB*CC*CC];
__device__ __align__(16) bf16  g_E1lo[(size_t)BB*CC*CC];
__device__ float g_att[(size_t)BB*CC*CC];   // energy -> softmax att -> Y=F.G
__device__ __align__(16) bf16  g_atthi[(size_t)BB*CC*CC]; // att/colsum split
__device__ __align__(16) bf16  g_attlo[(size_t)BB*CC*CC];
__device__ __align__(16) bf16  g_Mhi[(size_t)BB*CC*CC];   // M split [o][c]
__device__ __align__(16) bf16  g_Mlo[(size_t)BB*CC*CC];
__device__ __align__(16) bf16  g_Fhi[(size_t)BB*CC*CC];   // Weff = Wt - M.Wv split
__device__ __align__(16) bf16  g_Flo[(size_t)BB*CC*CC];
__device__ float g_beff[BB*CC];             // bt - M.bv
__device__ float g_colsum[BB*CC];
__device__ float g_sx[BB*CC];               // s_b[c] = sum_n x[b,n,c]
__device__ float g_scale[CC];
__device__ float g_shift[CC];

// Stage: Ahi(16K) Alo(16K) Bhi(8K) Blo(8K) = 48KB
#define ST_ALO 16384
#define ST_BHI 32768
#define ST_BLO 40960
#define STAGE  49152
#define SDYN2  (2*STAGE)

// ---------------- helpers ---------------------------------------------------
__device__ __forceinline__ uint32_t smem_u32(const void* p){
    uint32_t a;
    asm("{ .reg .u64 t; cvta.to.shared.u64 t, %1; cvt.u32.u64 %0, t; }" : "=r"(a) : "l"(p));
    return a;
}
__device__ __forceinline__ uint32_t sw128(uint32_t o){ return o ^ ((o >> 3) & 0x70); }

__device__ __forceinline__ void ldm4(uint32_t* r, uint32_t addr){
    asm volatile("ldmatrix.sync.aligned.m8n8.x4.shared.b16 {%0,%1,%2,%3}, [%4];"
        : "=r"(r[0]), "=r"(r[1]), "=r"(r[2]), "=r"(r[3]) : "r"(addr));
}
__device__ __forceinline__ void mma_bf16(float* c, const uint32_t* a, const uint32_t* b){
    asm volatile("mma.sync.aligned.m16n8k16.row.col.f32.bf16.bf16.f32 "
        "{%0,%1,%2,%3}, {%4,%5,%6,%7}, {%8,%9}, {%0,%1,%2,%3};"
        : "+f"(c[0]), "+f"(c[1]), "+f"(c[2]), "+f"(c[3])
        : "r"(a[0]), "r"(a[1]), "r"(a[2]), "r"(a[3]), "r"(b[0]), "r"(b[1]));
}
__device__ __forceinline__ void cpa16(uint32_t dst, const void* src){
    asm volatile("cp.async.cg.shared.global [%0], [%1], 16;" :: "r"(dst), "l"(src));
}
__device__ __forceinline__ void split_store(bf16* hi, bf16* lo, size_t i, float v){
    bf16 h = __float2bfloat16(v);
    hi[i] = h;
    lo[i] = __float2bfloat16(v - __bfloat162float(h));
}
__device__ __forceinline__ void split_pair(float v0, float v1, uint32_t& hi, uint32_t& lo){
    bf16 h0 = __float2bfloat16(v0), h1 = __float2bfloat16(v1);
    float r0 = v0 - __bfloat162float(h0), r1 = v1 - __bfloat162float(h1);
    __nv_bfloat162 ph; ph.x = h0; ph.y = h1;
    __nv_bfloat162 pl = __floats2bfloat162_rn(r0, r1);
    hi = *(uint32_t*)&ph;
    lo = *(uint32_t*)&pl;
}

// ---------------------------------------------------------------------------
// Split-bf16 128(M)x64(N) GEMM building blocks; NS-stage cp.async pipeline.
// ---------------------------------------------------------------------------
__device__ __forceinline__ void ld_chunk(char* smem, int stage, int tid,
        const bf16* __restrict__ Ahi, const bf16* __restrict__ Alo,
        const bf16* __restrict__ Bhi, const bf16* __restrict__ Blo,
        int ldA, int ldB, int c0){
    uint32_t sbase = smem_u32(smem) + stage * STAGE;
    #pragma unroll
    for (int i = 0; i < 4; i++){           // A: 128 rows x 8 segs
        int g = tid + i * 256;
        int row = g >> 3, cg = g & 7;
        uint32_t so = sw128((uint32_t)(row * 128 + cg * 16));
        size_t ga = (size_t)row * ldA + c0 + cg * 8;
        cpa16(sbase + so,          Ahi + ga);
        cpa16(sbase + ST_ALO + so, Alo + ga);
    }
    #pragma unroll
    for (int i = 0; i < 2; i++){           // B: 64 rows x 8 segs
        int g = tid + i * 256;
        int row = g >> 3, cg = g & 7;
        uint32_t so = sw128((uint32_t)(row * 128 + cg * 16));
        size_t gb = (size_t)row * ldB + c0 + cg * 8;
        cpa16(sbase + ST_BHI + so, Bhi + gb);
        cpa16(sbase + ST_BLO + so, Blo + gb);
    }
    asm volatile("cp.async.commit_group;" ::: "memory");
}

__device__ __forceinline__ void compute_chunk(uint32_t sb, int lane,
        int warpM, int warpN, float acc[2][4][4]){
    #pragma unroll
    for (int ks = 0; ks < 4; ks++){
        uint32_t ahi[2][4], alo[2][4];
        #pragma unroll
        for (int mf = 0; mf < 2; mf++){
            int row = warpM * 32 + mf * 16 + (lane & 15);
            uint32_t off = sw128((uint32_t)(row * 128 + ks * 32 + (lane >> 4) * 16));
            ldm4(ahi[mf], sb + off);
            ldm4(alo[mf], sb + ST_ALO + off);
        }
        #pragma unroll
        for (int ng = 0; ng < 2; ng++){
            int rowb = warpN * 32 + ng * 16 + (lane & 15);
            uint32_t off = sw128((uint32_t)(rowb * 128 + ks * 32 + (lane >> 4) * 16));
            uint32_t bh[4], bl[4];
            ldm4(bh, sb + ST_BHI + off);
            ldm4(bl, sb + ST_BLO + off);
            uint32_t bh0[2] = {bh[0], bh[2]}, bh1[2] = {bh[1], bh[3]};
            uint32_t bl0[2] = {bl[0], bl[2]}, bl1[2] = {bl[1], bl[3]};
            #pragma unroll
            for (int mf = 0; mf < 2; mf++){
                mma_bf16(acc[mf][ng*2],     ahi[mf], bh0);
                mma_bf16(acc[mf][ng*2],     ahi[mf], bl0);
                mma_bf16(acc[mf][ng*2],     alo[mf], bh0);
                mma_bf16(acc[mf][ng*2 + 1], ahi[mf], bh1);
                mma_bf16(acc[mf][ng*2 + 1], ahi[mf], bl1);
                mma_bf16(acc[mf][ng*2 + 1], alo[mf], bh1);
            }
        }
    }
}

template<int NS>
__device__ __forceinline__ void gemm_main(char* smem,
        const bf16* __restrict__ Ahi, const bf16* __restrict__ Alo, int ldA,
        const bf16* __restrict__ Bhi, const bf16* __restrict__ Blo, int ldB,
        int nChunks, float acc[2][4][4])
{
    int tid = threadIdx.x, lane = tid & 31, wid = tid >> 5;
    int warpM = wid & 3, warpN = wid >> 2;
    uint32_t sb0 = smem_u32(smem);

    int issued = 0, ldst = 0, cst = 0;
    int npre = (nChunks < NS - 1) ? nChunks : (NS - 1);
    for (int i = 0; i < npre; i++){
        ld_chunk(smem, ldst, tid, Ahi, Alo, Bhi, Blo, ldA, ldB, issued * 64);
        issued++; ldst = (ldst + 1 == NS) ? 0 : ldst + 1;
    }
    for (int cc = 0; cc < nChunks; cc++){
        if (issued < nChunks){
            ld_chunk(smem, ldst, tid, Ahi, Alo, Bhi, Blo, ldA, ldB, issued * 64);
            issued++; ldst = (ldst + 1 == NS) ? 0 : ldst + 1;
        }
        int pend = issued - cc - 1;
        if (pend >= 2)      asm volatile("cp.async.wait_group 2;" ::: "memory");
        else if (pend == 1) asm volatile("cp.async.wait_group 1;" ::: "memory");
        else                asm volatile("cp.async.wait_group 0;" ::: "memory");
        __syncthreads();
        compute_chunk(sb0 + cst * STAGE, lane, warpM, warpN, acc);
        cst = (cst + 1 == NS) ? 0 : cst + 1;
        __syncthreads();
    }
}

// ---------------- conversion: x -> split x / split x^T / column sums --------
__global__ void __launch_bounds__(256) k_cvt_x(const float* __restrict__ x){
    int b = blockIdx.z, n0 = blockIdx.x * 64, c0 = blockIdx.y * 64;
    __shared__ float xs[64][65];
    int t = threadIdx.x;
    const float* xb = x + ((size_t)b * NN + n0) * CC + c0;
    #pragma unroll
    for (int p = 0; p < 4; p++){
        int row = p * 16 + (t >> 4);
        int c4  = (t & 15) * 4;
        float4 v = *(const float4*)(xb + (size_t)row * CC + c4);
        uint32_t h0, l0, h1, l1;
        split_pair(v.x, v.y, h0, l0);
        split_pair(v.z, v.w, h1, l1);
        size_t di = ((size_t)b * NN + n0 + row) * CC + c0 + c4;
        *(uint2*)(g_xhi + di) = make_uint2(h0, h1);
        *(uint2*)(g_xlo + di) = make_uint2(l0, l1);
        xs[row][c4 + 0] = v.x; xs[row][c4 + 1] = v.y;
        xs[row][c4 + 2] = v.z; xs[row][c4 + 3] = v.w;
    }
    __syncthreads();
    #pragma unroll
    for (int p = 0; p < 4; p++){
        int cl = p * 16 + (t >> 4);
        int n4 = (t & 15) * 4;
        float v0 = xs[n4][cl], v1 = xs[n4+1][cl], v2 = xs[n4+2][cl], v3 = xs[n4+3][cl];
        uint32_t h0, l0, h1, l1;
        split_pair(v0, v1, h0, l0);
        split_pair(v2, v3, h1, l1);
        size_t di = ((size_t)b * CC + c0 + cl) * NN + n0 + n4;
        *(uint2*)(g_xThi + di) = make_uint2(h0, h1);
        *(uint2*)(g_xTlo + di) = make_uint2(l0, l1);
    }
    // column sums for BN-from-G statistics
    if (t < 64){
        float s = 0.f;
        #pragma unroll 8
        for (int r2 = 0; r2 < 64; r2++) s += xs[r2][t];
        atomicAdd(&g_sx[b * CC + c0 + t], s);
    }
}
__global__ void k_cvt_w(const float* __restrict__ Wq, const float* __restrict__ Wv,
                        const float* __restrict__ Wt){
    // side duties: zero colsum + sx accumulators (this kernel precedes cvt_x)
    if (blockIdx.x < 16)                        g_colsum[blockIdx.x * 256 + threadIdx.x] = 0.f;
    if (blockIdx.x >= 17 && blockIdx.x < 33)    g_sx[(blockIdx.x - 17) * 256 + threadIdx.x] = 0.f;
    int idx = blockIdx.x * blockDim.x + threadIdx.x;
    int which = idx >> 16, rem = idx & 65535;
    const float* s = (which == 0) ? Wq : (which == 1) ? Wv : Wt;
    float v = s[rem];
    split_store(g_Whi, g_Wlo, idx, v);
    if (which == 1){
        int o = rem >> 8, c = rem & 255;          // Wv[o][c] -> WvT[c][o]
        split_store(g_WvThi, g_WvTlo, (size_t)c * CC + o, v);
    }
}

// ---------------- KTG: G = x^T x (split-K x3, symmetric: 6 of 8 tiles) ------
// 2-stage, 2 CTAs/SM: 288 CTAs on 296 slots = one full wave
__constant__ int c_tileC[6] = {0, 0, 0, 0, 128, 128};
__constant__ int c_tileD[6] = {0, 64, 128, 192, 128, 192};
__constant__ int c_ks0[3] = {0, 22, 43};    // chunk start (64-wide chunks)
__constant__ int c_ksn[3] = {22, 21, 21};   // chunk count
__global__ void __launch_bounds__(256, 2)
ktG(){
    extern __shared__ char smem[];
    int b = blockIdx.z / 3, ks = blockIdx.z % 3;
    int cBase = c_tileC[blockIdx.x], dBase = c_tileD[blockIdx.x];
    size_t kOff = (size_t)c_ks0[ks] * 64;
    int nch = c_ksn[ks];
    const bf16* Ah = g_xThi + ((size_t)b * CC + cBase) * NN + kOff;
    const bf16* Al = g_xTlo + ((size_t)b * CC + cBase) * NN + kOff;
    const bf16* Bh = g_xThi + ((size_t)b * CC + dBase) * NN + kOff;
    const bf16* Bl = g_xTlo + ((size_t)b * CC + dBase) * NN + kOff;
    float acc[2][4][4] = {};
    gemm_main<2>(smem, Ah, Al, NN, Bh, Bl, NN, nch, acc);

    int tid = threadIdx.x, lane = tid & 31, wid = tid >> 5;
    int warpM = wid & 3, warpN = wid >> 2;
    int gr = lane >> 2, gc = (lane & 3) * 2;
    float* dst = g_Gp + ((size_t)(ks * BB + b)) * CC * CC;
    #pragma unroll
    for (int mf = 0; mf < 2; mf++)
        #pragma unroll
        for (int nf = 0; nf < 4; nf++){
            float* c = acc[mf][nf];
            int row0 = warpM * 32 + mf * 16 + gr;
            int col  = warpN * 32 + nf * 8 + gc;
            #pragma unroll
            for (int h = 0; h < 2; h++)
                *(float2*)(dst + (size_t)(cBase + row0 + h*8) * CC + dBase + col)
                    = make_float2(c[2*h], c[2*h+1]);
        }
}
// sum split-K partials; mirror the uncomputed lower-left quadrant (r>=128,c<128)
__global__ void k_gsum(){
    size_t i = ((size_t)blockIdx.x * blockDim.x + threadIdx.x) * 4;
    const size_t S = (size_t)BB * CC * CC;
    int rc = (int)(i & 65535);
    int r = rc >> 8, c0 = rc & 255;
    int b = (int)(i >> 16);
    float v[4];
    if (r >= 128 && c0 < 128){
        #pragma unroll
        for (int j = 0; j < 4; j++){
            size_t src = (size_t)b * CC * CC + (size_t)(c0 + j) * CC + r;  // transposed
            v[j] = g_Gp[src] + g_Gp[S + src] + g_Gp[2*S + src];
        }
    } else {
        float4 a = *(const float4*)(g_Gp + i);
        float4 bb = *(const float4*)(g_Gp + S + i);
        float4 cc = *(const float4*)(g_Gp + 2*S + i);
        v[0] = a.x+bb.x+cc.x; v[1] = a.y+bb.y+cc.y;
        v[2] = a.z+bb.z+cc.z; v[3] = a.w+bb.w+cc.w;
    }
    uint32_t h0,l0,h1,l1;
    split_pair(v[0],v[1],h0,l0); split_pair(v[2],v[3],h1,l1);
    *(uint2*)(g_Ghi + i) = make_uint2(h0,h1);
    *(uint2*)(g_Glo + i) = make_uint2(l0,l1);
}

// ---------------- small square GEMMs (K=256) --------------------------------
// mode 0: E1 = Wq.G            -> split E1
// mode 1: E  = E1.Wq^T         -> fp32 g_att
// mode 2: M  = Wt.attS         -> split M
// mode 3: Weff = Wt - M.Wv     -> split F; nBase==0 CTAs also compute beff
// mode 4: Y  = F.G             -> fp32 g_att (for BN stats; G symmetric)
__global__ void __launch_bounds__(256, 2)
ksq(int mode, const float* __restrict__ Wt,
    const float* __restrict__ bt, const float* __restrict__ bv){
    extern __shared__ char smem[];
    int b = blockIdx.z;
    int mBase = blockIdx.y * 128, nBase = blockIdx.x * 64;
    size_t boff = (size_t)b * CC * CC;
    const bf16 *Ah, *Al, *Bh, *Bl;
    if (mode == 0){
        Ah = g_Whi + mBase * CC;        Al = g_Wlo + mBase * CC;
        Bh = g_Ghi + boff + nBase * CC; Bl = g_Glo + boff + nBase * CC;
    } else if (mode == 1){
        Ah = g_E1hi + boff + mBase * CC; Al = g_E1lo + boff + mBase * CC;
        Bh = g_Whi + nBase * CC;         Bl = g_Wlo + nBase * CC;
    } else if (mode == 2){
        Ah = g_Whi + 2*CC*CC + mBase * CC; Al = g_Wlo + 2*CC*CC + mBase * CC;
        Bh = g_atthi + boff + nBase * CC;  Bl = g_attlo + boff + nBase * CC;
    } else if (mode == 3){
        Ah = g_Mhi + boff + mBase * CC;  Al = g_Mlo + boff + mBase * CC;
        Bh = g_WvThi + nBase * CC;       Bl = g_WvTlo + nBase * CC;
    } else {
        Ah = g_Fhi + boff + mBase * CC;  Al = g_Flo + boff + mBase * CC;
        Bh = g_Ghi + boff + nBase * CC;  Bl = g_Glo + boff + nBase * CC;
    }
    float acc[2][4][4] = {};
    gemm_main<2>(smem, Ah, Al, CC, Bh, Bl, CC, 4, acc);

    int tid = threadIdx.x, lane = tid & 31, wid = tid >> 5;
    int warpM = wid & 3, warpN = wid >> 2;
    int gr = lane >> 2, gc = (lane & 3) * 2;
    #pragma unroll
    for (int mf = 0; mf < 2; mf++)
        #pragma unroll
        for (int nf = 0; nf < 4; nf++){
            float* c = acc[mf][nf];
            int row0 = warpM * 32 + mf * 16 + gr;
            int col  = warpN * 32 + nf * 8 + gc;
            #pragma unroll
            for (int h = 0; h < 2; h++){
                int rr = mBase + row0 + h*8, kk = nBase + col;
                size_t di = boff + (size_t)rr * CC + kk;
                if (mode == 1 || mode == 4){
                    *(float2*)(g_att + di) = make_float2(c[2*h], c[2*h+1]);
                } else if (mode == 0){
                    uint32_t hi, lo;
                    split_pair(c[2*h], c[2*h+1], hi, lo);
                    *(uint32_t*)(g_E1hi + di) = hi; *(uint32_t*)(g_E1lo + di) = lo;
                } else if (mode == 2){
                    uint32_t hi, lo;
                    split_pair(c[2*h], c[2*h+1], hi, lo);
                    *(uint32_t*)(g_Mhi + di) = hi; *(uint32_t*)(g_Mlo + di) = lo;
                } else {
                    float w0 = Wt[(size_t)rr * CC + kk];
                    float w1 = Wt[(size_t)rr * CC + kk + 1];
                    uint32_t hi, lo;
                    split_pair(w0 - c[2*h], w1 - c[2*h+1], hi, lo);
                    *(uint32_t*)(g_Fhi + di) = hi; *(uint32_t*)(g_Flo + di) = lo;
                }
            }
        }
    // fused beff: one CTA column per (b, mBase) computes beff rows
    if (mode == 3 && blockIdx.x == 0 && tid < 128){
        int o = mBase + tid;
        const bf16* mh = g_Mhi + boff + (size_t)o * CC;
        const bf16* ml = g_Mlo + boff + (size_t)o * CC;
        float s = 0.f;
        for (int c = 0; c < CC; c++)
            s += (__bfloat162float(mh[c]) + __bfloat162float(ml[c])) * bv[c];
        g_beff[b * CC + o] = bt[o] - s;
    }
}

// ---------------- softmax (+ fused colsum) / att scaling --------------------
__global__ void k_softmax(){
    size_t row = blockIdx.x;
    float* p = g_att + row * CC;
    int t = threadIdx.x, lane = t & 31, w = t >> 5;
    float v = p[t];
    __shared__ float wred[8];
    float m = v;
    #pragma unroll
    for (int o = 16; o > 0; o >>= 1) m = fmaxf(m, __shfl_xor_sync(0xffffffffu, m, o));
    if (lane == 0) wred[w] = m;
    __syncthreads();
    float mx = wred[0];
    #pragma unroll
    for (int i = 1; i < 8; i++) mx = fmaxf(mx, wred[i]);
    float e = __expf(v - mx);
    float s = e;
    #pragma unroll
    for (int o = 16; o > 0; o >>= 1) s += __shfl_xor_sync(0xffffffffu, s, o);
    __syncthreads();
    if (lane == 0) wred[w] = s;
    __syncthreads();
    float tot = 0.f;
    #pragma unroll
    for (int i = 0; i < 8; i++) tot += wred[i];
    float val = e / tot;
    p[t] = val;
    int b = (int)(row >> 8);
    atomicAdd(&g_colsum[b * CC + t], val);      // fused column sum
}
// attS = att / (1e-9 + colsum[d]), split to bf16
__global__ void k_scaleAtt(){
    size_t i = ((size_t)blockIdx.x * blockDim.x + threadIdx.x) * 4;
    int b = (int)(i >> 16);
    int d = (int)(i & 255);
    float4 a  = *(const float4*)(g_att + i);
    float4 cs = *(const float4*)(g_colsum + b * CC + d);
    float v0 = a.x / (1e-9f + cs.x), v1 = a.y / (1e-9f + cs.y);
    float v2 = a.z / (1e-9f + cs.z), v3 = a.w / (1e-9f + cs.w);
    uint32_t h0,l0,h1,l1;
    split_pair(v0,v1,h0,l0); split_pair(v2,v3,h1,l1);
    *(uint2*)(g_atthi + i) = make_uint2(h0,h1);
    *(uint2*)(g_attlo + i) = make_uint2(l0,l1);
}

// ---------------- BN stats from G: per-channel scale/shift ------------------
// sum_t[o]  = sum_b ( s_b.F_b[o] + N*beff[b,o] )
// sumsq[o]  = sum_b ( Y[b,o,:].F_b[o,:] + 2 beff (s_b.F_b[o]) + N beff^2 )
__global__ void k_bnfin2(const float* __restrict__ gamma, const float* __restrict__ beta){
    int o = blockIdx.x, t = threadIdx.x, lane = t & 31, w = t >> 5;
    __shared__ float rq[8], rl[8];
    float sum_t = 0.f, sumsq = 0.f;
    for (int b = 0; b < BB; b++){
        size_t ro = (size_t)b * CC * CC + (size_t)o * CC;
        float F = __bfloat162float(g_Fhi[ro + t]) + __bfloat162float(g_Flo[ro + t]);
        float ql = g_att[ro + t] * F;          // Y.F
        float ll = g_sx[b * CC + t] * F;       // s.F
        #pragma unroll
        for (int off = 16; off > 0; off >>= 1){
            ql += __shfl_xor_sync(0xffffffffu, ql, off);
            ll += __shfl_xor_sync(0xffffffffu, ll, off);
        }
        if (lane == 0){ rq[w] = ql; rl[w] = ll; }
        __syncthreads();
        if (t == 0){
            float q = 0.f, l = 0.f;
            #pragma unroll
            for (int i = 0; i < 8; i++){ q += rq[i]; l += rl[i]; }
            float be = g_beff[b * CC + o];
            sum_t += l + (float)NN * be;
            sumsq += q + 2.f * be * l + (float)NN * be * be;
        }
        __syncthreads();
    }
    if (t == 0){
        float inv = 1.0f / (float)(BB * NN);
        float mean = sum_t * inv;
        float var  = sumsq * inv - mean * mean;
        float rstd = rsqrtf(var + 1e-5f);
        float sc = gamma[o] * rstd;
        g_scale[o] = sc;
        g_shift[o] = beta[o] - mean * sc;
    }
}

// ---------------- KT7: out = x + relu(scale*(x.Weff^T + beff) + shift) ------
__global__ void __launch_bounds__(256, 2)
kt7(const float* __restrict__ x, float* __restrict__ out){
    extern __shared__ char smem[];
    int b = blockIdx.z;
    int mBase = blockIdx.x * 128;   // n
    int oBase = blockIdx.y * 64;    // o
    const bf16* Ah = g_xhi + ((size_t)b * NN + mBase) * CC;
    const bf16* Al = g_xlo + ((size_t)b * NN + mBase) * CC;
    const bf16* Bh = g_Fhi + ((size_t)b * CC + oBase) * CC;
    const bf16* Bl = g_Flo + ((size_t)b * CC + oBase) * CC;
    float acc[2][4][4] = {};
    gemm_main<2>(smem, Ah, Al, CC, Bh, Bl, CC, 4, acc);

    int tid = threadIdx.x, lane = tid & 31, wid = tid >> 5;
    int warpM = wid & 3, warpN = wid >> 2;
    int gr = lane >> 2, gc = (lane & 3) * 2;
    #pragma unroll
    for (int nf = 0; nf < 4; nf++){
        int col = warpN * 32 + nf * 8 + gc;
        int o = oBase + col;
        float be0 = g_beff[b * CC + o], be1 = g_beff[b * CC + o + 1];
        float sc0 = g_scale[o], sc1 = g_scale[o + 1];
        float sh0 = g_shift[o], sh1 = g_shift[o + 1];
        #pragma unroll
        for (int mf = 0; mf < 2; mf++){
            float* c = acc[mf][nf];
            int row0 = warpM * 32 + mf * 16 + gr;
            #pragma unroll
            for (int h = 0; h < 2; h++){
                int n = mBase + row0 + h * 8;
                size_t di = ((size_t)b * NN + n) * CC + o;
                float t0 = c[2*h] + be0, t1 = c[2*h+1] + be1;
                float2 xv = *(const float2*)(x + di);
                float r0 = xv.x + fmaxf(fmaf(t0, sc0, sh0), 0.f);
                float r1 = xv.y + fmaxf(fmaf(t1, sc1, sh1), 0.f);
                *(float2*)(out + di) = make_float2(r0, r1);
            }
        }
    }
}

// ---------------- launch ----------------------------------------------------
extern "C" void kernel_launch(void* const* d_in, const int* in_sizes, int n_in,
                              void* d_out, int out_size){
    (void)in_sizes; (void)n_in; (void)out_size;
    const float* x     = (const float*)d_in[1];
    const float* Wq    = (const float*)d_in[2];
    const float* Wv    = (const float*)d_in[3];
    const float* bv    = (const float*)d_in[4];
    const float* Wt    = (const float*)d_in[5];
    const float* bt    = (const float*)d_in[6];
    const float* gamma = (const float*)d_in[7];
    const float* beta  = (const float*)d_in[8];
    float* out = (float*)d_out;

    static bool init_done = false;
    if (!init_done){
        cudaFuncSetAttribute(ktG, cudaFuncAttributeMaxDynamicSharedMemorySize, SDYN2);
        cudaFuncSetAttribute(ksq, cudaFuncAttributeMaxDynamicSharedMemorySize, SDYN2);
        cudaFuncSetAttribute(kt7, cudaFuncAttributeMaxDynamicSharedMemorySize, SDYN2);
        init_done = true;
    }

    k_cvt_w   <<<768, 256>>>(Wq, Wv, Wt);           // also zeros colsum, sx
    k_cvt_x   <<<dim3(64, 4, BB), 256>>>(x);
    ktG       <<<dim3(6, 1, 3*BB), 256, SDYN2>>>();
    k_gsum    <<<1024, 256>>>();
    ksq       <<<dim3(4, 2, BB), 256, SDYN2>>>(0, Wt, bt, bv);
    ksq       <<<dim3(4, 2, BB), 256, SDYN2>>>(1, Wt, bt, bv);
    k_softmax <<<BB*CC, 256>>>();
    k_scaleAtt<<<1024, 256>>>();
    ksq       <<<dim3(4, 2, BB), 256, SDYN2>>>(2, Wt, bt, bv);
    ksq       <<<dim3(4, 2, BB), 256, SDYN2>>>(3, Wt, bt, bv);
    ksq       <<<dim3(4, 2, BB), 256, SDYN2>>>(4, Wt, bt, bv);
    k_bnfin2  <<<CC, 256>>>(gamma, beta);
    kt7       <<<dim3(32, 4, BB), 256, SDYN2>>>(x, out);
}

// round 15
// speedup vs baseline: 1.1783x; 1.0237x over previous
#include <cuda_runtime.h>
#include <cuda_bf16.h>
#include <cstdint>

#define BB 16
#define NN 4096
#define CC 256

using bf16 = __nv_bfloat16;

// ---------------- scratch (device globals; no allocation allowed) ----------
__device__ __align__(16) bf16  g_xhi[(size_t)BB*NN*CC];   // x split, [B][N][C]
__device__ __align__(16) bf16  g_xlo[(size_t)BB*NN*CC];
__device__ __align__(16) bf16  g_xThi[(size_t)BB*CC*NN];  // x^T split, [B][C][N]
__device__ __align__(16) bf16  g_xTlo[(size_t)BB*CC*NN];
__device__ __align__(16) bf16  g_Whi[3*CC*CC];            // Wq, Wv, Wt split
__device__ __align__(16) bf16  g_Wlo[3*CC*CC];
__device__ __align__(16) bf16  g_WvThi[CC*CC];            // Wv^T split  [k][c]
__device__ __align__(16) bf16  g_WvTlo[CC*CC];
__device__ float g_Gp[(size_t)3*BB*CC*CC];  // split-K partials of G (3 ways)
__device__ __align__(16) bf16  g_Ghi[(size_t)BB*CC*CC];
__device__ __align__(16) bf16  g_Glo[(size_t)BB*CC*CC];
__device__ __align__(16) bf16  g_E1hi[(size_t)BB*CC*CC];
__device__ __align__(16) bf16  g_E1lo[(size_t)BB*CC*CC];
__device__ float g_att[(size_t)BB*CC*CC];   // energy -> softmax att -> Y=F.G
__device__ __align__(16) bf16  g_atthi[(size_t)BB*CC*CC]; // att/colsum split
__device__ __align__(16) bf16  g_attlo[(size_t)BB*CC*CC];
__device__ __align__(16) bf16  g_Mhi[(size_t)BB*CC*CC];   // M split [o][c]
__device__ __align__(16) bf16  g_Mlo[(size_t)BB*CC*CC];
__device__ __align__(16) bf16  g_Fhi[(size_t)BB*CC*CC];   // Weff = Wt - M.Wv split
__device__ __align__(16) bf16  g_Flo[(size_t)BB*CC*CC];
__device__ float g_beff[BB*CC];             // bt - M.bv
__device__ float g_colsum[BB*CC];
__device__ float g_sx[BB*CC];               // s_b[c] = sum_n x[b,n,c]
__device__ float g_scale[CC];
__device__ float g_shift[CC];

// 128x64 stage: Ahi(16K) Alo(16K) Bhi(8K) Blo(8K) = 48KB
#define ST_ALO 16384
#define ST_BHI 32768
#define ST_BLO 40960
#define STAGE  49152
#define SDYN2  (2*STAGE)
// 64x64 stage: Ahi(8K) Alo(8K) Bhi(8K) Blo(8K) = 32KB
#define S64_ALO 8192
#define S64_BHI 16384
#define S64_BLO 24576
#define STAGE64 32768
#define SDYN64  (2*STAGE64)

// ---------------- helpers ---------------------------------------------------
__device__ __forceinline__ uint32_t smem_u32(const void* p){
    uint32_t a;
    asm("{ .reg .u64 t; cvta.to.shared.u64 t, %1; cvt.u32.u64 %0, t; }" : "=r"(a) : "l"(p));
    return a;
}
__device__ __forceinline__ uint32_t sw128(uint32_t o){ return o ^ ((o >> 3) & 0x70); }

__device__ __forceinline__ void ldm4(uint32_t* r, uint32_t addr){
    asm volatile("ldmatrix.sync.aligned.m8n8.x4.shared.b16 {%0,%1,%2,%3}, [%4];"
        : "=r"(r[0]), "=r"(r[1]), "=r"(r[2]), "=r"(r[3]) : "r"(addr));
}
__device__ __forceinline__ void mma_bf16(float* c, const uint32_t* a, const uint32_t* b){
    asm volatile("mma.sync.aligned.m16n8k16.row.col.f32.bf16.bf16.f32 "
        "{%0,%1,%2,%3}, {%4,%5,%6,%7}, {%8,%9}, {%0,%1,%2,%3};"
        : "+f"(c[0]), "+f"(c[1]), "+f"(c[2]), "+f"(c[3])
        : "r"(a[0]), "r"(a[1]), "r"(a[2]), "r"(a[3]), "r"(b[0]), "r"(b[1]));
}
__device__ __forceinline__ void cpa16(uint32_t dst, const void* src){
    asm volatile("cp.async.cg.shared.global [%0], [%1], 16;" :: "r"(dst), "l"(src));
}
__device__ __forceinline__ void split_store(bf16* hi, bf16* lo, size_t i, float v){
    bf16 h = __float2bfloat16(v);
    hi[i] = h;
    lo[i] = __float2bfloat16(v - __bfloat162float(h));
}
__device__ __forceinline__ void split_pair(float v0, float v1, uint32_t& hi, uint32_t& lo){
    bf16 h0 = __float2bfloat16(v0), h1 = __float2bfloat16(v1);
    float r0 = v0 - __bfloat162float(h0), r1 = v1 - __bfloat162float(h1);
    __nv_bfloat162 ph; ph.x = h0; ph.y = h1;
    __nv_bfloat162 pl = __floats2bfloat162_rn(r0, r1);
    hi = *(uint32_t*)&ph;
    lo = *(uint32_t*)&pl;
}

// ---------------------------------------------------------------------------
// 128(M)x64(N) split-bf16 GEMM (used by ktG, kt7). 2-stage cp.async.
// ---------------------------------------------------------------------------
__device__ __forceinline__ void ld_chunk(char* smem, int stage, int tid,
        const bf16* __restrict__ Ahi, const bf16* __restrict__ Alo,
        const bf16* __restrict__ Bhi, const bf16* __restrict__ Blo,
        int ldA, int ldB, int c0){
    uint32_t sbase = smem_u32(smem) + stage * STAGE;
    #pragma unroll
    for (int i = 0; i < 4; i++){           // A: 128 rows x 8 segs
        int g = tid + i * 256;
        int row = g >> 3, cg = g & 7;
        uint32_t so = sw128((uint32_t)(row * 128 + cg * 16));
        size_t ga = (size_t)row * ldA + c0 + cg * 8;
        cpa16(sbase + so,          Ahi + ga);
        cpa16(sbase + ST_ALO + so, Alo + ga);
    }
    #pragma unroll
    for (int i = 0; i < 2; i++){           // B: 64 rows x 8 segs
        int g = tid + i * 256;
        int row = g >> 3, cg = g & 7;
        uint32_t so = sw128((uint32_t)(row * 128 + cg * 16));
        size_t gb = (size_t)row * ldB + c0 + cg * 8;
        cpa16(sbase + ST_BHI + so, Bhi + gb);
        cpa16(sbase + ST_BLO + so, Blo + gb);
    }
    asm volatile("cp.async.commit_group;" ::: "memory");
}

__device__ __forceinline__ void compute_chunk(uint32_t sb, int lane,
        int warpM, int warpN, float acc[2][4][4]){
    #pragma unroll
    for (int ks = 0; ks < 4; ks++){
        uint32_t ahi[2][4], alo[2][4];
        #pragma unroll
        for (int mf = 0; mf < 2; mf++){
            int row = warpM * 32 + mf * 16 + (lane & 15);
            uint32_t off = sw128((uint32_t)(row * 128 + ks * 32 + (lane >> 4) * 16));
            ldm4(ahi[mf], sb + off);
            ldm4(alo[mf], sb + ST_ALO + off);
        }
        #pragma unroll
        for (int ng = 0; ng < 2; ng++){
            int rowb = warpN * 32 + ng * 16 + (lane & 15);
            uint32_t off = sw128((uint32_t)(rowb * 128 + ks * 32 + (lane >> 4) * 16));
            uint32_t bh[4], bl[4];
            ldm4(bh, sb + ST_BHI + off);
            ldm4(bl, sb + ST_BLO + off);
            uint32_t bh0[2] = {bh[0], bh[2]}, bh1[2] = {bh[1], bh[3]};
            uint32_t bl0[2] = {bl[0], bl[2]}, bl1[2] = {bl[1], bl[3]};
            #pragma unroll
            for (int mf = 0; mf < 2; mf++){
                mma_bf16(acc[mf][ng*2],     ahi[mf], bh0);
                mma_bf16(acc[mf][ng*2],     ahi[mf], bl0);
                mma_bf16(acc[mf][ng*2],     alo[mf], bh0);
                mma_bf16(acc[mf][ng*2 + 1], ahi[mf], bh1);
                mma_bf16(acc[mf][ng*2 + 1], ahi[mf], bl1);
                mma_bf16(acc[mf][ng*2 + 1], alo[mf], bh1);
            }
        }
    }
}

__device__ __forceinline__ void gemm_main(char* smem,
        const bf16* __restrict__ Ahi, const bf16* __restrict__ Alo, int ldA,
        const bf16* __restrict__ Bhi, const bf16* __restrict__ Blo, int ldB,
        int nChunks, float acc[2][4][4])
{
    int tid = threadIdx.x, lane = tid & 31, wid = tid >> 5;
    int warpM = wid & 3, warpN = wid >> 2;
    uint32_t sb0 = smem_u32(smem);

    ld_chunk(smem, 0, tid, Ahi, Alo, Bhi, Blo, ldA, ldB, 0);
    for (int cc = 0; cc < nChunks; cc++){
        if (cc + 1 < nChunks){
            ld_chunk(smem, (cc + 1) & 1, tid, Ahi, Alo, Bhi, Blo, ldA, ldB, (cc + 1) * 64);
            asm volatile("cp.async.wait_group 1;" ::: "memory");
        } else {
            asm volatile("cp.async.wait_group 0;" ::: "memory");
        }
        __syncthreads();
        compute_chunk(sb0 + (cc & 1) * STAGE, lane, warpM, warpN, acc);
        __syncthreads();
    }
}

// ---------------------------------------------------------------------------
// 64(M)x64(N) split-bf16 GEMM (chain GEMMs). warps 2(M) x 4(N), warp 32x16.
// ---------------------------------------------------------------------------
__device__ __forceinline__ void ld_chunk64(char* smem, int stage, int tid,
        const bf16* __restrict__ Ahi, const bf16* __restrict__ Alo,
        const bf16* __restrict__ Bhi, const bf16* __restrict__ Blo,
        int c0){
    uint32_t sbase = smem_u32(smem) + stage * STAGE64;
    #pragma unroll
    for (int i = 0; i < 2; i++){           // A,B: 64 rows x 8 segs each
        int g = tid + i * 256;
        int row = g >> 3, cg = g & 7;
        uint32_t so = sw128((uint32_t)(row * 128 + cg * 16));
        size_t off = (size_t)row * CC + c0 + cg * 8;
        cpa16(sbase + so,           Ahi + off);
        cpa16(sbase + S64_ALO + so, Alo + off);
        cpa16(sbase + S64_BHI + so, Bhi + off);
        cpa16(sbase + S64_BLO + so, Blo + off);
    }
    asm volatile("cp.async.commit_group;" ::: "memory");
}

__device__ __forceinline__ void gemm_main64(char* smem,
        const bf16* __restrict__ Ahi, const bf16* __restrict__ Alo,
        const bf16* __restrict__ Bhi, const bf16* __restrict__ Blo,
        float acc[2][2][4])
{
    int tid = threadIdx.x, lane = tid & 31, wid = tid >> 5;
    int warpM = wid & 1, warpN = wid >> 1;
    uint32_t sb0 = smem_u32(smem);

    ld_chunk64(smem, 0, tid, Ahi, Alo, Bhi, Blo, 0);
    for (int cc = 0; cc < 4; cc++){
        if (cc + 1 < 4){
            ld_chunk64(smem, (cc + 1) & 1, tid, Ahi, Alo, Bhi, Blo, (cc + 1) * 64);
            asm volatile("cp.async.wait_group 1;" ::: "memory");
        } else {
            asm volatile("cp.async.wait_group 0;" ::: "memory");
        }
        __syncthreads();
        uint32_t sb = sb0 + (cc & 1) * STAGE64;
        #pragma unroll
        for (int ks = 0; ks < 4; ks++){
            uint32_t ahi[2][4], alo[2][4];
            #pragma unroll
            for (int mf = 0; mf < 2; mf++){
                int row = warpM * 32 + mf * 16 + (lane & 15);
                uint32_t off = sw128((uint32_t)(row * 128 + ks * 32 + (lane >> 4) * 16));
                ldm4(ahi[mf], sb + off);
                ldm4(alo[mf], sb + S64_ALO + off);
            }
            int rowb = warpN * 16 + (lane & 15);
            uint32_t offb = sw128((uint32_t)(rowb * 128 + ks * 32 + (lane >> 4) * 16));
            uint32_t bh[4], bl[4];
            ldm4(bh, sb + S64_BHI + offb);
            ldm4(bl, sb + S64_BLO + offb);
            uint32_t bh0[2] = {bh[0], bh[2]}, bh1[2] = {bh[1], bh[3]};
            uint32_t bl0[2] = {bl[0], bl[2]}, bl1[2] = {bl[1], bl[3]};
            #pragma unroll
            for (int mf = 0; mf < 2; mf++){
                mma_bf16(acc[mf][0], ahi[mf], bh0);
                mma_bf16(acc[mf][0], ahi[mf], bl0);
                mma_bf16(acc[mf][0], alo[mf], bh0);
                mma_bf16(acc[mf][1], ahi[mf], bh1);
                mma_bf16(acc[mf][1], ahi[mf], bl1);
                mma_bf16(acc[mf][1], alo[mf], bh1);
            }
        }
        __syncthreads();
    }
}

// ---------------- conversion: x -> split x / split x^T / column sums --------
__global__ void __launch_bounds__(256) k_cvt_x(const float* __restrict__ x){
    int b = blockIdx.z, n0 = blockIdx.x * 64, c0 = blockIdx.y * 64;
    __shared__ float xs[64][65];
    int t = threadIdx.x;
    const float* xb = x + ((size_t)b * NN + n0) * CC + c0;
    #pragma unroll
    for (int p = 0; p < 4; p++){
        int row = p * 16 + (t >> 4);
        int c4  = (t & 15) * 4;
        float4 v = *(const float4*)(xb + (size_t)row * CC + c4);
        uint32_t h0, l0, h1, l1;
        split_pair(v.x, v.y, h0, l0);
        split_pair(v.z, v.w, h1, l1);
        size_t di = ((size_t)b * NN + n0 + row) * CC + c0 + c4;
        *(uint2*)(g_xhi + di) = make_uint2(h0, h1);
        *(uint2*)(g_xlo + di) = make_uint2(l0, l1);
        xs[row][c4 + 0] = v.x; xs[row][c4 + 1] = v.y;
        xs[row][c4 + 2] = v.z; xs[row][c4 + 3] = v.w;
    }
    __syncthreads();
    #pragma unroll
    for (int p = 0; p < 4; p++){
        int cl = p * 16 + (t >> 4);
        int n4 = (t & 15) * 4;
        float v0 = xs[n4][cl], v1 = xs[n4+1][cl], v2 = xs[n4+2][cl], v3 = xs[n4+3][cl];
        uint32_t h0, l0, h1, l1;
        split_pair(v0, v1, h0, l0);
        split_pair(v2, v3, h1, l1);
        size_t di = ((size_t)b * CC + c0 + cl) * NN + n0 + n4;
        *(uint2*)(g_xThi + di) = make_uint2(h0, h1);
        *(uint2*)(g_xTlo + di) = make_uint2(l0, l1);
    }
    // column sums for BN-from-G statistics
    if (t < 64){
        float s = 0.f;
        #pragma unroll 8
        for (int r2 = 0; r2 < 64; r2++) s += xs[r2][t];
        atomicAdd(&g_sx[b * CC + c0 + t], s);
    }
}
__global__ void k_cvt_w(const float* __restrict__ Wq, const float* __restrict__ Wv,
                        const float* __restrict__ Wt){
    // side duties: zero colsum + sx accumulators (this kernel precedes cvt_x)
    if (blockIdx.x < 16)                        g_colsum[blockIdx.x * 256 + threadIdx.x] = 0.f;
    if (blockIdx.x >= 17 && blockIdx.x < 33)    g_sx[(blockIdx.x - 17) * 256 + threadIdx.x] = 0.f;
    int idx = blockIdx.x * blockDim.x + threadIdx.x;
    int which = idx >> 16, rem = idx & 65535;
    const float* s = (which == 0) ? Wq : (which == 1) ? Wv : Wt;
    float v = s[rem];
    split_store(g_Whi, g_Wlo, idx, v);
    if (which == 1){
        int o = rem >> 8, c = rem & 255;          // Wv[o][c] -> WvT[c][o]
        split_store(g_WvThi, g_WvTlo, (size_t)c * CC + o, v);
    }
}

// ---------------- KTG: G = x^T x (split-K x3, symmetric: 6 of 8 tiles) ------
__constant__ int c_tileC[6] = {0, 0, 0, 0, 128, 128};
__constant__ int c_tileD[6] = {0, 64, 128, 192, 128, 192};
__constant__ int c_ks0[3] = {0, 22, 43};    // chunk start (64-wide chunks)
__constant__ int c_ksn[3] = {22, 21, 21};   // chunk count
__global__ void __launch_bounds__(256, 2)
ktG(){
    extern __shared__ char smem[];
    int b = blockIdx.z / 3, ks = blockIdx.z % 3;
    int cBase = c_tileC[blockIdx.x], dBase = c_tileD[blockIdx.x];
    size_t kOff = (size_t)c_ks0[ks] * 64;
    int nch = c_ksn[ks];
    const bf16* Ah = g_xThi + ((size_t)b * CC + cBase) * NN + kOff;
    const bf16* Al = g_xTlo + ((size_t)b * CC + cBase) * NN + kOff;
    const bf16* Bh = g_xThi + ((size_t)b * CC + dBase) * NN + kOff;
    const bf16* Bl = g_xTlo + ((size_t)b * CC + dBase) * NN + kOff;
    float acc[2][4][4] = {};
    gemm_main(smem, Ah, Al, NN, Bh, Bl, NN, nch, acc);

    int tid = threadIdx.x, lane = tid & 31, wid = tid >> 5;
    int warpM = wid & 3, warpN = wid >> 2;
    int gr = lane >> 2, gc = (lane & 3) * 2;
    float* dst = g_Gp + ((size_t)(ks * BB + b)) * CC * CC;
    #pragma unroll
    for (int mf = 0; mf < 2; mf++)
        #pragma unroll
        for (int nf = 0; nf < 4; nf++){
            float* c = acc[mf][nf];
            int row0 = warpM * 32 + mf * 16 + gr;
            int col  = warpN * 32 + nf * 8 + gc;
            #pragma unroll
            for (int h = 0; h < 2; h++)
                *(float2*)(dst + (size_t)(cBase + row0 + h*8) * CC + dBase + col)
                    = make_float2(c[2*h], c[2*h+1]);
        }
}
// sum split-K partials; mirror the uncomputed lower-left quadrant (r>=128,c<128)
__global__ void k_gsum(){
    size_t i = ((size_t)blockIdx.x * blockDim.x + threadIdx.x) * 4;
    const size_t S = (size_t)BB * CC * CC;
    int rc = (int)(i & 65535);
    int r = rc >> 8, c0 = rc & 255;
    int b = (int)(i >> 16);
    float v[4];
    if (r >= 128 && c0 < 128){
        #pragma unroll
        for (int j = 0; j < 4; j++){
            size_t src = (size_t)b * CC * CC + (size_t)(c0 + j) * CC + r;  // transposed
            v[j] = g_Gp[src] + g_Gp[S + src] + g_Gp[2*S + src];
        }
    } else {
        float4 a = *(const float4*)(g_Gp + i);
        float4 bb = *(const float4*)(g_Gp + S + i);
        float4 cc = *(const float4*)(g_Gp + 2*S + i);
        v[0] = a.x+bb.x+cc.x; v[1] = a.y+bb.y+cc.y;
        v[2] = a.z+bb.z+cc.z; v[3] = a.w+bb.w+cc.w;
    }
    uint32_t h0,l0,h1,l1;
    split_pair(v[0],v[1],h0,l0); split_pair(v[2],v[3],h1,l1);
    *(uint2*)(g_Ghi + i) = make_uint2(h0,h1);
    *(uint2*)(g_Glo + i) = make_uint2(l0,l1);
}

// ---------------- chain GEMMs (64x64 tiles, grid 4x4x16) --------------------
// mode 0: E1 = Wq.G            -> split E1
// mode 1: E  = E1.Wq^T         -> fp32 g_att
// mode 2: M  = Wt.attS         -> split M
// mode 3: Weff = Wt - M.Wv     -> split F; nBase==0 CTAs also compute beff
// mode 4: Y  = F.G             -> fp32 g_att (BN stats; G symmetric)
__global__ void __launch_bounds__(256, 2)
ksq(int mode, const float* __restrict__ Wt,
    const float* __restrict__ bt, const float* __restrict__ bv){
    extern __shared__ char smem[];
    int b = blockIdx.z;
    int mBase = blockIdx.y * 64, nBase = blockIdx.x * 64;
    size_t boff = (size_t)b * CC * CC;
    const bf16 *Ah, *Al, *Bh, *Bl;
    if (mode == 0){
        Ah = g_Whi + mBase * CC;        Al = g_Wlo + mBase * CC;
        Bh = g_Ghi + boff + nBase * CC; Bl = g_Glo + boff + nBase * CC;
    } else if (mode == 1){
        Ah = g_E1hi + boff + mBase * CC; Al = g_E1lo + boff + mBase * CC;
        Bh = g_Whi + nBase * CC;         Bl = g_Wlo + nBase * CC;
    } else if (mode == 2){
        Ah = g_Whi + 2*CC*CC + mBase * CC; Al = g_Wlo + 2*CC*CC + mBase * CC;
        Bh = g_atthi + boff + nBase * CC;  Bl = g_attlo + boff + nBase * CC;
    } else if (mode == 3){
        Ah = g_Mhi + boff + mBase * CC;  Al = g_Mlo + boff + mBase * CC;
        Bh = g_WvThi + nBase * CC;       Bl = g_WvTlo + nBase * CC;
    } else {
        Ah = g_Fhi + boff + mBase * CC;  Al = g_Flo + boff + mBase * CC;
        Bh = g_Ghi + boff + nBase * CC;  Bl = g_Glo + boff + nBase * CC;
    }
    float acc[2][2][4] = {};
    gemm_main64(smem, Ah, Al, Bh, Bl, acc);

    int tid = threadIdx.x, lane = tid & 31, wid = tid >> 5;
    int warpM = wid & 1, warpN = wid >> 1;
    int gr = lane >> 2, gc = (lane & 3) * 2;
    #pragma unroll
    for (int mf = 0; mf < 2; mf++)
        #pragma unroll
        for (int nf = 0; nf < 2; nf++){
            float* c = acc[mf][nf];
            int row0 = warpM * 32 + mf * 16 + gr;
            int col  = warpN * 16 + nf * 8 + gc;
            #pragma unroll
            for (int h = 0; h < 2; h++){
                int rr = mBase + row0 + h*8, kk = nBase + col;
                size_t di = boff + (size_t)rr * CC + kk;
                if (mode == 1 || mode == 4){
                    *(float2*)(g_att + di) = make_float2(c[2*h], c[2*h+1]);
                } else if (mode == 0){
                    uint32_t hi, lo;
                    split_pair(c[2*h], c[2*h+1], hi, lo);
                    *(uint32_t*)(g_E1hi + di) = hi; *(uint32_t*)(g_E1lo + di) = lo;
                } else if (mode == 2){
                    uint32_t hi, lo;
                    split_pair(c[2*h], c[2*h+1], hi, lo);
                    *(uint32_t*)(g_Mhi + di) = hi; *(uint32_t*)(g_Mlo + di) = lo;
                } else {
                    float w0 = Wt[(size_t)rr * CC + kk];
                    float w1 = Wt[(size_t)rr * CC + kk + 1];
                    uint32_t hi, lo;
                    split_pair(w0 - c[2*h], w1 - c[2*h+1], hi, lo);
                    *(uint32_t*)(g_Fhi + di) = hi; *(uint32_t*)(g_Flo + di) = lo;
                }
            }
        }
    // fused beff: nBase==0 CTAs compute beff rows [mBase, mBase+64)
    if (mode == 3 && blockIdx.x == 0 && tid < 64){
        int o = mBase + tid;
        const bf16* mh = g_Mhi + boff + (size_t)o * CC;
        const bf16* ml = g_Mlo + boff + (size_t)o * CC;
        float s = 0.f;
        for (int c = 0; c < CC; c++)
            s += (__bfloat162float(mh[c]) + __bfloat162float(ml[c])) * bv[c];
        g_beff[b * CC + o] = bt[o] - s;
    }
}

// ---------------- softmax (+ fused colsum) / att scaling --------------------
__global__ void k_softmax(){
    size_t row = blockIdx.x;
    float* p = g_att + row * CC;
    int t = threadIdx.x, lane = t & 31, w = t >> 5;
    float v = p[t];
    __shared__ float wred[8];
    float m = v;
    #pragma unroll
    for (int o = 16; o > 0; o >>= 1) m = fmaxf(m, __shfl_xor_sync(0xffffffffu, m, o));
    if (lane == 0) wred[w] = m;
    __syncthreads();
    float mx = wred[0];
    #pragma unroll
    for (int i = 1; i < 8; i++) mx = fmaxf(mx, wred[i]);
    float e = __expf(v - mx);
    float s = e;
    #pragma unroll
    for (int o = 16; o > 0; o >>= 1) s += __shfl_xor_sync(0xffffffffu, s, o);
    __syncthreads();
    if (lane == 0) wred[w] = s;
    __syncthreads();
    float tot = 0.f;
    #pragma unroll
    for (int i = 0; i < 8; i++) tot += wred[i];
    float val = e / tot;
    p[t] = val;
    int b = (int)(row >> 8);
    atomicAdd(&g_colsum[b * CC + t], val);      // fused column sum
}
// attS = att / (1e-9 + colsum[d]), split to bf16
__global__ void k_scaleAtt(){
    size_t i = ((size_t)blockIdx.x * blockDim.x + threadIdx.x) * 4;
    int b = (int)(i >> 16);
    int d = (int)(i & 255);
    float4 a  = *(const float4*)(g_att + i);
    float4 cs = *(const float4*)(g_colsum + b * CC + d);
    float v0 = a.x / (1e-9f + cs.x), v1 = a.y / (1e-9f + cs.y);
    float v2 = a.z / (1e-9f + cs.z), v3 = a.w / (1e-9f + cs.w);
    uint32_t h0,l0,h1,l1;
    split_pair(v0,v1,h0,l0); split_pair(v2,v3,h1,l1);
    *(uint2*)(g_atthi + i) = make_uint2(h0,h1);
    *(uint2*)(g_attlo + i) = make_uint2(l0,l1);
}

// ---------------- BN stats from G: per-channel scale/shift ------------------
__global__ void k_bnfin2(const float* __restrict__ gamma, const float* __restrict__ beta){
    int o = blockIdx.x, t = threadIdx.x, lane = t & 31, w = t >> 5;
    __shared__ float rq[8], rl[8];
    float sum_t = 0.f, sumsq = 0.f;
    for (int b = 0; b < BB; b++){
        size_t ro = (size_t)b * CC * CC + (size_t)o * CC;
        float F = __bfloat162float(g_Fhi[ro + t]) + __bfloat162float(g_Flo[ro + t]);
        float ql = g_att[ro + t] * F;          // Y.F
        float ll = g_sx[b * CC + t] * F;       // s.F
        #pragma unroll
        for (int off = 16; off > 0; off >>= 1){
            ql += __shfl_xor_sync(0xffffffffu, ql, off);
            ll += __shfl_xor_sync(0xffffffffu, ll, off);
        }
        if (lane == 0){ rq[w] = ql; rl[w] = ll; }
        __syncthreads();
        if (t == 0){
            float q = 0.f, l = 0.f;
            #pragma unroll
            for (int i = 0; i < 8; i++){ q += rq[i]; l += rl[i]; }
            float be = g_beff[b * CC + o];
            sum_t += l + (float)NN * be;
            sumsq += q + 2.f * be * l + (float)NN * be * be;
        }
        __syncthreads();
    }
    if (t == 0){
        float inv = 1.0f / (float)(BB * NN);
        float mean = sum_t * inv;
        float var  = sumsq * inv - mean * mean;
        float rstd = rsqrtf(var + 1e-5f);
        float sc = gamma[o] * rstd;
        g_scale[o] = sc;
        g_shift[o] = beta[o] - mean * sc;
    }
}

// ---------------- KT7: out = x + relu(scale*(x.Weff^T + beff) + shift) ------
__global__ void __launch_bounds__(256, 2)
kt7(const float* __restrict__ x, float* __restrict__ out){
    extern __shared__ char smem[];
    int b = blockIdx.z;
    int mBase = blockIdx.x * 128;   // n
    int oBase = blockIdx.y * 64;    // o
    const bf16* Ah = g_xhi + ((size_t)b * NN + mBase) * CC;
    const bf16* Al = g_xlo + ((size_t)b * NN + mBase) * CC;
    const bf16* Bh = g_Fhi + ((size_t)b * CC + oBase) * CC;
    const bf16* Bl = g_Flo + ((size_t)b * CC + oBase) * CC;
    float acc[2][4][4] = {};
    gemm_main(smem, Ah, Al, CC, Bh, Bl, CC, 4, acc);

    int tid = threadIdx.x, lane = tid & 31, wid = tid >> 5;
    int warpM = wid & 3, warpN = wid >> 2;
    int gr = lane >> 2, gc = (lane & 3) * 2;
    #pragma unroll
    for (int nf = 0; nf < 4; nf++){
        int col = warpN * 32 + nf * 8 + gc;
        int o = oBase + col;
        float be0 = g_beff[b * CC + o], be1 = g_beff[b * CC + o + 1];
        float sc0 = g_scale[o], sc1 = g_scale[o + 1];
        float sh0 = g_shift[o], sh1 = g_shift[o + 1];
        #pragma unroll
        for (int mf = 0; mf < 2; mf++){
            float* c = acc[mf][nf];
            int row0 = warpM * 32 + mf * 16 + gr;
            #pragma unroll
            for (int h = 0; h < 2; h++){
                int n = mBase + row0 + h * 8;
                size_t di = ((size_t)b * NN + n) * CC + o;
                float t0 = c[2*h] + be0, t1 = c[2*h+1] + be1;
                float2 xv = *(const float2*)(x + di);
                float r0 = xv.x + fmaxf(fmaf(t0, sc0, sh0), 0.f);
                float r1 = xv.y + fmaxf(fmaf(t1, sc1, sh1), 0.f);
                *(float2*)(out + di) = make_float2(r0, r1);
            }
        }
    }
}

// ---------------- launch ----------------------------------------------------
extern "C" void kernel_launch(void* const* d_in, const int* in_sizes, int n_in,
                              void* d_out, int out_size){
    (void)in_sizes; (void)n_in; (void)out_size;
    const float* x     = (const float*)d_in[1];
    const float* Wq    = (const float*)d_in[2];
    const float* Wv    = (const float*)d_in[3];
    const float* bv    = (const float*)d_in[4];
    const float* Wt    = (const float*)d_in[5];
    const float* bt    = (const float*)d_in[6];
    const float* gamma = (const float*)d_in[7];
    const float* beta  = (const float*)d_in[8];
    float* out = (float*)d_out;

    static bool init_done = false;
    if (!init_done){
        cudaFuncSetAttribute(ktG, cudaFuncAttributeMaxDynamicSharedMemorySize, SDYN2);
        cudaFuncSetAttribute(ksq, cudaFuncAttributeMaxDynamicSharedMemorySize, SDYN64);
        cudaFuncSetAttribute(kt7, cudaFuncAttributeMaxDynamicSharedMemorySize, SDYN2);
        init_done = true;
    }

    k_cvt_w   <<<768, 256>>>(Wq, Wv, Wt);           // also zeros colsum, sx
    k_cvt_x   <<<dim3(64, 4, BB), 256>>>(x);
    ktG       <<<dim3(6, 1, 3*BB), 256, SDYN2>>>();
    k_gsum    <<<1024, 256>>>();
    ksq       <<<dim3(4, 4, BB), 256, SDYN64>>>(0, Wt, bt, bv);
    ksq       <<<dim3(4, 4, BB), 256, SDYN64>>>(1, Wt, bt, bv);
    k_softmax <<<BB*CC, 256>>>();
    k_scaleAtt<<<1024, 256>>>();
    ksq       <<<dim3(4, 4, BB), 256, SDYN64>>>(2, Wt, bt, bv);
    ksq       <<<dim3(4, 4, BB), 256, SDYN64>>>(3, Wt, bt, bv);
    ksq       <<<dim3(4, 4, BB), 256, SDYN64>>>(4, Wt, bt, bv);
    k_bnfin2  <<<CC, 256>>>(gamma, beta);
    kt7       <<<dim3(32, 4, BB), 256, SDYN2>>>(x, out);
}

// round 16
// speedup vs baseline: 1.2254x; 1.0400x over previous
#include <cuda_runtime.h>
#include <cuda_bf16.h>
#include <cstdint>

#define BB 16
#define NN 4096
#define CC 256

using bf16 = __nv_bfloat16;

// ---------------- scratch (device globals; no allocation allowed) ----------
__device__ __align__(16) bf16  g_xhi[(size_t)BB*NN*CC];   // x split, [B][N][C]
__device__ __align__(16) bf16  g_xlo[(size_t)BB*NN*CC];
__device__ __align__(16) bf16  g_Whi[3*CC*CC];            // Wq, Wv, Wt split
__device__ __align__(16) bf16  g_Wlo[3*CC*CC];
__device__ __align__(16) bf16  g_WvThi[CC*CC];            // Wv^T split  [k][c]
__device__ __align__(16) bf16  g_WvTlo[CC*CC];
__device__ float g_Gp[(size_t)3*BB*CC*CC];  // split-K partials of G (3 ways)
__device__ __align__(16) bf16  g_Ghi[(size_t)BB*CC*CC];
__device__ __align__(16) bf16  g_Glo[(size_t)BB*CC*CC];
__device__ __align__(16) bf16  g_E1hi[(size_t)BB*CC*CC];
__device__ __align__(16) bf16  g_E1lo[(size_t)BB*CC*CC];
__device__ float g_att[(size_t)BB*CC*CC];   // energy -> softmax att -> Y=F.G
__device__ __align__(16) bf16  g_atthi[(size_t)BB*CC*CC]; // att/colsum split
__device__ __align__(16) bf16  g_attlo[(size_t)BB*CC*CC];
__device__ __align__(16) bf16  g_Mhi[(size_t)BB*CC*CC];   // M split [o][c]
__device__ __align__(16) bf16  g_Mlo[(size_t)BB*CC*CC];
__device__ __align__(16) bf16  g_Fhi[(size_t)BB*CC*CC];   // Weff = Wt - M.Wv split
__device__ __align__(16) bf16  g_Flo[(size_t)BB*CC*CC];
__device__ float g_beff[BB*CC];             // bt - M.bv
__device__ float g_colsum[BB*CC];
__device__ float g_sx[BB*CC];               // s_b[c] = sum_n x[b,n,c]
__device__ float g_scale[CC];
__device__ float g_shift[CC];

// 128x64 stage: Ahi(16K) Alo(16K) Bhi(8K) Blo(8K) = 48KB
#define ST_ALO 16384
#define ST_BHI 32768
#define ST_BLO 40960
#define STAGE  49152
#define SDYN2  (2*STAGE)
// 64x64 stage: Ahi(8K) Alo(8K) Bhi(8K) Blo(8K) = 32KB
#define S64_ALO 8192
#define S64_BHI 16384
#define S64_BLO 24576
#define STAGE64 32768
#define SDYN64  (2*STAGE64)

// ---------------- helpers ---------------------------------------------------
__device__ __forceinline__ uint32_t smem_u32(const void* p){
    uint32_t a;
    asm("{ .reg .u64 t; cvta.to.shared.u64 t, %1; cvt.u32.u64 %0, t; }" : "=r"(a) : "l"(p));
    return a;
}
__device__ __forceinline__ uint32_t sw128(uint32_t o){ return o ^ ((o >> 3) & 0x70); }

__device__ __forceinline__ void ldm4(uint32_t* r, uint32_t addr){
    asm volatile("ldmatrix.sync.aligned.m8n8.x4.shared.b16 {%0,%1,%2,%3}, [%4];"
        : "=r"(r[0]), "=r"(r[1]), "=r"(r[2]), "=r"(r[3]) : "r"(addr));
}
__device__ __forceinline__ void ldm4t(uint32_t* r, uint32_t addr){
    asm volatile("ldmatrix.sync.aligned.m8n8.x4.trans.shared.b16 {%0,%1,%2,%3}, [%4];"
        : "=r"(r[0]), "=r"(r[1]), "=r"(r[2]), "=r"(r[3]) : "r"(addr));
}
__device__ __forceinline__ void mma_bf16(float* c, const uint32_t* a, const uint32_t* b){
    asm volatile("mma.sync.aligned.m16n8k16.row.col.f32.bf16.bf16.f32 "
        "{%0,%1,%2,%3}, {%4,%5,%6,%7}, {%8,%9}, {%0,%1,%2,%3};"
        : "+f"(c[0]), "+f"(c[1]), "+f"(c[2]), "+f"(c[3])
        : "r"(a[0]), "r"(a[1]), "r"(a[2]), "r"(a[3]), "r"(b[0]), "r"(b[1]));
}
__device__ __forceinline__ void cpa16(uint32_t dst, const void* src){
    asm volatile("cp.async.cg.shared.global [%0], [%1], 16;" :: "r"(dst), "l"(src));
}
__device__ __forceinline__ void split_store(bf16* hi, bf16* lo, size_t i, float v){
    bf16 h = __float2bfloat16(v);
    hi[i] = h;
    lo[i] = __float2bfloat16(v - __bfloat162float(h));
}
__device__ __forceinline__ void split_pair(float v0, float v1, uint32_t& hi, uint32_t& lo){
    bf16 h0 = __float2bfloat16(v0), h1 = __float2bfloat16(v1);
    float r0 = v0 - __bfloat162float(h0), r1 = v1 - __bfloat162float(h1);
    __nv_bfloat162 ph; ph.x = h0; ph.y = h1;
    __nv_bfloat162 pl = __floats2bfloat162_rn(r0, r1);
    hi = *(uint32_t*)&ph;
    lo = *(uint32_t*)&pl;
}

// ---------------------------------------------------------------------------
// 128(M)x64(N) split-bf16 GEMM (kt7). 2-stage cp.async. A,B K-major.
// ---------------------------------------------------------------------------
__device__ __forceinline__ void ld_chunk(char* smem, int stage, int tid,
        const bf16* __restrict__ Ahi, const bf16* __restrict__ Alo,
        const bf16* __restrict__ Bhi, const bf16* __restrict__ Blo,
        int ldA, int ldB, int c0){
    uint32_t sbase = smem_u32(smem) + stage * STAGE;
    #pragma unroll
    for (int i = 0; i < 4; i++){           // A: 128 rows x 8 segs
        int g = tid + i * 256;
        int row = g >> 3, cg = g & 7;
        uint32_t so = sw128((uint32_t)(row * 128 + cg * 16));
        size_t ga = (size_t)row * ldA + c0 + cg * 8;
        cpa16(sbase + so,          Ahi + ga);
        cpa16(sbase + ST_ALO + so, Alo + ga);
    }
    #pragma unroll
    for (int i = 0; i < 2; i++){           // B: 64 rows x 8 segs
        int g = tid + i * 256;
        int row = g >> 3, cg = g & 7;
        uint32_t so = sw128((uint32_t)(row * 128 + cg * 16));
        size_t gb = (size_t)row * ldB + c0 + cg * 8;
        cpa16(sbase + ST_BHI + so, Bhi + gb);
        cpa16(sbase + ST_BLO + so, Blo + gb);
    }
    asm volatile("cp.async.commit_group;" ::: "memory");
}

__device__ __forceinline__ void compute_chunk(uint32_t sb, int lane,
        int warpM, int warpN, float acc[2][4][4]){
    #pragma unroll
    for (int ks = 0; ks < 4; ks++){
        uint32_t ahi[2][4], alo[2][4];
        #pragma unroll
        for (int mf = 0; mf < 2; mf++){
            int row = warpM * 32 + mf * 16 + (lane & 15);
            uint32_t off = sw128((uint32_t)(row * 128 + ks * 32 + (lane >> 4) * 16));
            ldm4(ahi[mf], sb + off);
            ldm4(alo[mf], sb + ST_ALO + off);
        }
        #pragma unroll
        for (int ng = 0; ng < 2; ng++){
            int rowb = warpN * 32 + ng * 16 + (lane & 15);
            uint32_t off = sw128((uint32_t)(rowb * 128 + ks * 32 + (lane >> 4) * 16));
            uint32_t bh[4], bl[4];
            ldm4(bh, sb + ST_BHI + off);
            ldm4(bl, sb + ST_BLO + off);
            uint32_t bh0[2] = {bh[0], bh[2]}, bh1[2] = {bh[1], bh[3]};
            uint32_t bl0[2] = {bl[0], bl[2]}, bl1[2] = {bl[1], bl[3]};
            #pragma unroll
            for (int mf = 0; mf < 2; mf++){
                mma_bf16(acc[mf][ng*2],     ahi[mf], bh0);
                mma_bf16(acc[mf][ng*2],     ahi[mf], bl0);
                mma_bf16(acc[mf][ng*2],     alo[mf], bh0);
                mma_bf16(acc[mf][ng*2 + 1], ahi[mf], bh1);
                mma_bf16(acc[mf][ng*2 + 1], ahi[mf], bl1);
                mma_bf16(acc[mf][ng*2 + 1], alo[mf], bh1);
            }
        }
    }
}

__device__ __forceinline__ void gemm_main(char* smem,
        const bf16* __restrict__ Ahi, const bf16* __restrict__ Alo, int ldA,
        const bf16* __restrict__ Bhi, const bf16* __restrict__ Blo, int ldB,
        int nChunks, float acc[2][4][4])
{
    int tid = threadIdx.x, lane = tid & 31, wid = tid >> 5;
    int warpM = wid & 3, warpN = wid >> 2;
    uint32_t sb0 = smem_u32(smem);

    ld_chunk(smem, 0, tid, Ahi, Alo, Bhi, Blo, ldA, ldB, 0);
    for (int cc = 0; cc < nChunks; cc++){
        if (cc + 1 < nChunks){
            ld_chunk(smem, (cc + 1) & 1, tid, Ahi, Alo, Bhi, Blo, ldA, ldB, (cc + 1) * 64);
            asm volatile("cp.async.wait_group 1;" ::: "memory");
        } else {
            asm volatile("cp.async.wait_group 0;" ::: "memory");
        }
        __syncthreads();
        compute_chunk(sb0 + (cc & 1) * STAGE, lane, warpM, warpN, acc);
        __syncthreads();
    }
}

// ---------------------------------------------------------------------------
// 64(M)x64(N) split-bf16 GEMM (chain GEMMs). warps 2(M) x 4(N), warp 32x16.
// ---------------------------------------------------------------------------
__device__ __forceinline__ void ld_chunk64(char* smem, int stage, int tid,
        const bf16* __restrict__ Ahi, const bf16* __restrict__ Alo,
        const bf16* __restrict__ Bhi, const bf16* __restrict__ Blo,
        int c0){
    uint32_t sbase = smem_u32(smem) + stage * STAGE64;
    #pragma unroll
    for (int i = 0; i < 2; i++){           // A,B: 64 rows x 8 segs each
        int g = tid + i * 256;
        int row = g >> 3, cg = g & 7;
        uint32_t so = sw128((uint32_t)(row * 128 + cg * 16));
        size_t off = (size_t)row * CC + c0 + cg * 8;
        cpa16(sbase + so,           Ahi + off);
        cpa16(sbase + S64_ALO + so, Alo + off);
        cpa16(sbase + S64_BHI + so, Bhi + off);
        cpa16(sbase + S64_BLO + so, Blo + off);
    }
    asm volatile("cp.async.commit_group;" ::: "memory");
}

__device__ __forceinline__ void gemm_main64(char* smem,
        const bf16* __restrict__ Ahi, const bf16* __restrict__ Alo,
        const bf16* __restrict__ Bhi, const bf16* __restrict__ Blo,
        float acc[2][2][4])
{
    int tid = threadIdx.x, lane = tid & 31, wid = tid >> 5;
    int warpM = wid & 1, warpN = wid >> 1;
    uint32_t sb0 = smem_u32(smem);

    ld_chunk64(smem, 0, tid, Ahi, Alo, Bhi, Blo, 0);
    for (int cc = 0; cc < 4; cc++){
        if (cc + 1 < 4){
            ld_chunk64(smem, (cc + 1) & 1, tid, Ahi, Alo, Bhi, Blo, (cc + 1) * 64);
            asm volatile("cp.async.wait_group 1;" ::: "memory");
        } else {
            asm volatile("cp.async.wait_group 0;" ::: "memory");
        }
        __syncthreads();
        uint32_t sb = sb0 + (cc & 1) * STAGE64;
        #pragma unroll
        for (int ks = 0; ks < 4; ks++){
            uint32_t ahi[2][4], alo[2][4];
            #pragma unroll
            for (int mf = 0; mf < 2; mf++){
                int row = warpM * 32 + mf * 16 + (lane & 15);
                uint32_t off = sw128((uint32_t)(row * 128 + ks * 32 + (lane >> 4) * 16));
                ldm4(ahi[mf], sb + off);
                ldm4(alo[mf], sb + S64_ALO + off);
            }
            int rowb = warpN * 16 + (lane & 15);
            uint32_t offb = sw128((uint32_t)(rowb * 128 + ks * 32 + (lane >> 4) * 16));
            uint32_t bh[4], bl[4];
            ldm4(bh, sb + S64_BHI + offb);
            ldm4(bl, sb + S64_BLO + offb);
            uint32_t bh0[2] = {bh[0], bh[2]}, bh1[2] = {bh[1], bh[3]};
            uint32_t bl0[2] = {bl[0], bl[2]}, bl1[2] = {bl[1], bl[3]};
            #pragma unroll
            for (int mf = 0; mf < 2; mf++){
                mma_bf16(acc[mf][0], ahi[mf], bh0);
                mma_bf16(acc[mf][0], ahi[mf], bl0);
                mma_bf16(acc[mf][0], alo[mf], bh0);
                mma_bf16(acc[mf][1], ahi[mf], bh1);
                mma_bf16(acc[mf][1], ahi[mf], bl1);
                mma_bf16(acc[mf][1], alo[mf], bh1);
            }
        }
        __syncthreads();
    }
}

// ---------------- conversion: x -> split x (streaming) + column sums --------
__global__ void __launch_bounds__(256) k_cvt_x(const float* __restrict__ x){
    int b = blockIdx.z, n0 = blockIdx.x * 64, c0 = blockIdx.y * 64;
    __shared__ float xs[16][68];
    int t = threadIdx.x;
    int nrow = t >> 4, c4 = (t & 15) * 4;
    const float* xb = x + ((size_t)b * NN + n0) * CC + c0;
    float s0 = 0.f, s1 = 0.f, s2 = 0.f, s3 = 0.f;
    #pragma unroll
    for (int p = 0; p < 4; p++){
        int row = p * 16 + nrow;
        float4 v = *(const float4*)(xb + (size_t)row * CC + c4);
        uint32_t h0, l0, h1, l1;
        split_pair(v.x, v.y, h0, l0);
        split_pair(v.z, v.w, h1, l1);
        size_t di = ((size_t)b * NN + n0 + row) * CC + c0 + c4;
        *(uint2*)(g_xhi + di) = make_uint2(h0, h1);
        *(uint2*)(g_xlo + di) = make_uint2(l0, l1);
        s0 += v.x; s1 += v.y; s2 += v.z; s3 += v.w;
    }
    xs[nrow][c4] = s0; xs[nrow][c4 + 1] = s1;
    xs[nrow][c4 + 2] = s2; xs[nrow][c4 + 3] = s3;
    __syncthreads();
    if (t < 64){
        float s = 0.f;
        #pragma unroll
        for (int r2 = 0; r2 < 16; r2++) s += xs[r2][t];
        atomicAdd(&g_sx[b * CC + c0 + t], s);
    }
}
__global__ void k_cvt_w(const float* __restrict__ Wq, const float* __restrict__ Wv,
                        const float* __restrict__ Wt){
    // side duties: zero colsum + sx accumulators (this kernel precedes cvt_x)
    if (blockIdx.x < 16)                        g_colsum[blockIdx.x * 256 + threadIdx.x] = 0.f;
    if (blockIdx.x >= 17 && blockIdx.x < 33)    g_sx[(blockIdx.x - 17) * 256 + threadIdx.x] = 0.f;
    int idx = blockIdx.x * blockDim.x + threadIdx.x;
    int which = idx >> 16, rem = idx & 65535;
    const float* s = (which == 0) ? Wq : (which == 1) ? Wv : Wt;
    float v = s[rem];
    split_store(g_Whi, g_Wlo, idx, v);
    if (which == 1){
        int o = rem >> 8, c = rem & 255;          // Wv[o][c] -> WvT[c][o]
        split_store(g_WvThi, g_WvTlo, (size_t)c * CC + o, v);
    }
}

// ---------------- KTG: G = x^T x via ldmatrix.trans on [N][C] x -------------
// A tile: c in [cBase,+128), B tile: c in [dBase,+64); K = n chunks of 64.
// smem A: 64 n-rows x 256B (swizzle cb ^ (n&7)<<4); B: 64 n-rows x 128B sw128.
__constant__ int c_tileC[6] = {0, 0, 0, 0, 128, 128};
__constant__ int c_tileD[6] = {0, 64, 128, 192, 128, 192};
__constant__ int c_ks0[3] = {0, 22, 43};    // chunk start (64-row chunks)
__constant__ int c_ksn[3] = {22, 21, 21};   // chunk count
__device__ __forceinline__ void ld_chunkT(char* smem, int stage, int tid,
        const bf16* __restrict__ Xh, const bf16* __restrict__ Xl,
        int cBase, int dBase, int nOff){
    uint32_t sbase = smem_u32(smem) + stage * STAGE;
    #pragma unroll
    for (int i = 0; i < 4; i++){           // A: 64 rows x 16 segs (256B rows)
        int g = tid + i * 256;
        int row = g >> 4, seg = g & 15;
        uint32_t so = (uint32_t)(row * 256 + ((seg * 16) ^ ((row & 7) << 4)));
        size_t src = (size_t)(nOff + row) * CC + cBase + seg * 8;
        cpa16(sbase + so,          Xh + src);
        cpa16(sbase + ST_ALO + so, Xl + src);
    }
    #pragma unroll
    for (int i = 0; i < 2; i++){           // B: 64 rows x 8 segs (128B rows)
        int g = tid + i * 256;
        int row = g >> 3, seg = g & 7;
        uint32_t so = sw128((uint32_t)(row * 128 + seg * 16));
        size_t src = (size_t)(nOff + row) * CC + dBase + seg * 8;
        cpa16(sbase + ST_BHI + so, Xh + src);
        cpa16(sbase + ST_BLO + so, Xl + src);
    }
    asm volatile("cp.async.commit_group;" ::: "memory");
}
__global__ void __launch_bounds__(256, 2)
ktG(){
    extern __shared__ char smem[];
    int b = blockIdx.z / 3, ks = blockIdx.z % 3;
    int cBase = c_tileC[blockIdx.x], dBase = c_tileD[blockIdx.x];
    int nOff0 = c_ks0[ks] * 64;
    int nch = c_ksn[ks];
    const bf16* Xh = g_xhi + (size_t)b * NN * CC;
    const bf16* Xl = g_xlo + (size_t)b * NN * CC;

    int tid = threadIdx.x, lane = tid & 31, wid = tid >> 5;
    int warpM = wid & 3, warpN = wid >> 2;
    uint32_t sb0 = smem_u32(smem);
    float acc[2][4][4] = {};

    ld_chunkT(smem, 0, tid, Xh, Xl, cBase, dBase, nOff0);
    for (int cc = 0; cc < nch; cc++){
        if (cc + 1 < nch){
            ld_chunkT(smem, (cc + 1) & 1, tid, Xh, Xl, cBase, dBase, nOff0 + (cc + 1) * 64);
            asm volatile("cp.async.wait_group 1;" ::: "memory");
        } else {
            asm volatile("cp.async.wait_group 0;" ::: "memory");
        }
        __syncthreads();
        uint32_t sb = sb0 + (cc & 1) * STAGE;
        #pragma unroll
        for (int ksn = 0; ksn < 4; ksn++){
            int n_l = ksn * 16 + (lane & 7) + ((lane >> 4) & 1) * 8;
            int chalf = ((lane >> 3) & 1) * 16;
            uint32_t ahi[2][4], alo[2][4];
            #pragma unroll
            for (int mf = 0; mf < 2; mf++){
                uint32_t cb = (uint32_t)((warpM * 32 + mf * 16) * 2 + chalf);
                uint32_t off = (uint32_t)(n_l * 256) + (cb ^ ((n_l & 7) << 4));
                ldm4t(ahi[mf], sb + off);
                ldm4t(alo[mf], sb + ST_ALO + off);
            }
            #pragma unroll
            for (int ng = 0; ng < 2; ng++){
                uint32_t cb = (uint32_t)((warpN * 32 + ng * 16) * 2 + chalf);
                uint32_t off = sw128((uint32_t)(n_l * 128) + cb);
                uint32_t bh[4], bl[4];
                ldm4t(bh, sb + ST_BHI + off);
                ldm4t(bl, sb + ST_BLO + off);
                uint32_t bh0[2] = {bh[0], bh[2]}, bh1[2] = {bh[1], bh[3]};
                uint32_t bl0[2] = {bl[0], bl[2]}, bl1[2] = {bl[1], bl[3]};
                #pragma unroll
                for (int mf = 0; mf < 2; mf++){
                    mma_bf16(acc[mf][ng*2],     ahi[mf], bh0);
                    mma_bf16(acc[mf][ng*2],     ahi[mf], bl0);
                    mma_bf16(acc[mf][ng*2],     alo[mf], bh0);
                    mma_bf16(acc[mf][ng*2 + 1], ahi[mf], bh1);
                    mma_bf16(acc[mf][ng*2 + 1], ahi[mf], bl1);
                    mma_bf16(acc[mf][ng*2 + 1], alo[mf], bh1);
                }
            }
        }
        __syncthreads();
    }

    int gr = lane >> 2, gc = (lane & 3) * 2;
    float* dst = g_Gp + ((size_t)(ks * BB + b)) * CC * CC;
    #pragma unroll
    for (int mf = 0; mf < 2; mf++)
        #pragma unroll
        for (int nf = 0; nf < 4; nf++){
            float* c = acc[mf][nf];
            int row0 = warpM * 32 + mf * 16 + gr;
            int col  = warpN * 32 + nf * 8 + gc;
            #pragma unroll
            for (int h = 0; h < 2; h++)
                *(float2*)(dst + (size_t)(cBase + row0 + h*8) * CC + dBase + col)
                    = make_float2(c[2*h], c[2*h+1]);
        }
}
// sum split-K partials; mirror the uncomputed lower-left quadrant (r>=128,c<128)
__global__ void k_gsum(){
    size_t i = ((size_t)blockIdx.x * blockDim.x + threadIdx.x) * 4;
    const size_t S = (size_t)BB * CC * CC;
    int rc = (int)(i & 65535);
    int r = rc >> 8, c0 = rc & 255;
    int b = (int)(i >> 16);
    float v[4];
    if (r >= 128 && c0 < 128){
        #pragma unroll
        for (int j = 0; j < 4; j++){
            size_t src = (size_t)b * CC * CC + (size_t)(c0 + j) * CC + r;  // transposed
            v[j] = g_Gp[src] + g_Gp[S + src] + g_Gp[2*S + src];
        }
    } else {
        float4 a = *(const float4*)(g_Gp + i);
        float4 bb = *(const float4*)(g_Gp + S + i);
        float4 cc = *(const float4*)(g_Gp + 2*S + i);
        v[0] = a.x+bb.x+cc.x; v[1] = a.y+bb.y+cc.y;
        v[2] = a.z+bb.z+cc.z; v[3] = a.w+bb.w+cc.w;
    }
    uint32_t h0,l0,h1,l1;
    split_pair(v[0],v[1],h0,l0); split_pair(v[2],v[3],h1,l1);
    *(uint2*)(g_Ghi + i) = make_uint2(h0,h1);
    *(uint2*)(g_Glo + i) = make_uint2(l0,l1);
}

// ---------------- chain GEMMs (64x64 tiles, grid 4x4x16) --------------------
// mode 0: E1 = Wq.G ; 1: E = E1.Wq^T (fp32) ; 2: M = Wt.attS ;
// mode 3: Weff = Wt - M.Wv (+beff) ; 4: Y = F.G (fp32, BN stats)
__global__ void __launch_bounds__(256, 2)
ksq(int mode, const float* __restrict__ Wt,
    const float* __restrict__ bt, const float* __restrict__ bv){
    extern __shared__ char smem[];
    int b = blockIdx.z;
    int mBase = blockIdx.y * 64, nBase = blockIdx.x * 64;
    size_t boff = (size_t)b * CC * CC;
    const bf16 *Ah, *Al, *Bh, *Bl;
    if (mode == 0){
        Ah = g_Whi + mBase * CC;        Al = g_Wlo + mBase * CC;
        Bh = g_Ghi + boff + nBase * CC; Bl = g_Glo + boff + nBase * CC;
    } else if (mode == 1){
        Ah = g_E1hi + boff + mBase * CC; Al = g_E1lo + boff + mBase * CC;
        Bh = g_Whi + nBase * CC;         Bl = g_Wlo + nBase * CC;
    } else if (mode == 2){
        Ah = g_Whi + 2*CC*CC + mBase * CC; Al = g_Wlo + 2*CC*CC + mBase * CC;
        Bh = g_atthi + boff + nBase * CC;  Bl = g_attlo + boff + nBase * CC;
    } else if (mode == 3){
        Ah = g_Mhi + boff + mBase * CC;  Al = g_Mlo + boff + mBase * CC;
        Bh = g_WvThi + nBase * CC;       Bl = g_WvTlo + nBase * CC;
    } else {
        Ah = g_Fhi + boff + mBase * CC;  Al = g_Flo + boff + mBase * CC;
        Bh = g_Ghi + boff + nBase * CC;  Bl = g_Glo + boff + nBase * CC;
    }
    float acc[2][2][4] = {};
    gemm_main64(smem, Ah, Al, Bh, Bl, acc);

    int tid = threadIdx.x, lane = tid & 31, wid = tid >> 5;
    int warpM = wid & 1, warpN = wid >> 1;
    int gr = lane >> 2, gc = (lane & 3) * 2;
    #pragma unroll
    for (int mf = 0; mf < 2; mf++)
        #pragma unroll
        for (int nf = 0; nf < 2; nf++){
            float* c = acc[mf][nf];
            int row0 = warpM * 32 + mf * 16 + gr;
            int col  = warpN * 16 + nf * 8 + gc;
            #pragma unroll
            for (int h = 0; h < 2; h++){
                int rr = mBase + row0 + h*8, kk = nBase + col;
                size_t di = boff + (size_t)rr * CC + kk;
                if (mode == 1 || mode == 4){
                    *(float2*)(g_att + di) = make_float2(c[2*h], c[2*h+1]);
                } else if (mode == 0){
                    uint32_t hi, lo;
                    split_pair(c[2*h], c[2*h+1], hi, lo);
                    *(uint32_t*)(g_E1hi + di) = hi; *(uint32_t*)(g_E1lo + di) = lo;
                } else if (mode == 2){
                    uint32_t hi, lo;
                    split_pair(c[2*h], c[2*h+1], hi, lo);
                    *(uint32_t*)(g_Mhi + di) = hi; *(uint32_t*)(g_Mlo + di) = lo;
                } else {
                    float w0 = Wt[(size_t)rr * CC + kk];
                    float w1 = Wt[(size_t)rr * CC + kk + 1];
                    uint32_t hi, lo;
                    split_pair(w0 - c[2*h], w1 - c[2*h+1], hi, lo);
                    *(uint32_t*)(g_Fhi + di) = hi; *(uint32_t*)(g_Flo + di) = lo;
                }
            }
        }
    if (mode == 3 && blockIdx.x == 0 && tid < 64){
        int o = mBase + tid;
        const bf16* mh = g_Mhi + boff + (size_t)o * CC;
        const bf16* ml = g_Mlo + boff + (size_t)o * CC;
        float s = 0.f;
        for (int c = 0; c < CC; c++)
            s += (__bfloat162float(mh[c]) + __bfloat162float(ml[c])) * bv[c];
        g_beff[b * CC + o] = bt[o] - s;
    }
}

// ---------------- softmax (+ fused colsum) / att scaling --------------------
__global__ void k_softmax(){
    size_t row = blockIdx.x;
    float* p = g_att + row * CC;
    int t = threadIdx.x, lane = t & 31, w = t >> 5;
    float v = p[t];
    __shared__ float wred[8];
    float m = v;
    #pragma unroll
    for (int o = 16; o > 0; o >>= 1) m = fmaxf(m, __shfl_xor_sync(0xffffffffu, m, o));
    if (lane == 0) wred[w] = m;
    __syncthreads();
    float mx = wred[0];
    #pragma unroll
    for (int i = 1; i < 8; i++) mx = fmaxf(mx, wred[i]);
    float e = __expf(v - mx);
    float s = e;
    #pragma unroll
    for (int o = 16; o > 0; o >>= 1) s += __shfl_xor_sync(0xffffffffu, s, o);
    __syncthreads();
    if (lane == 0) wred[w] = s;
    __syncthreads();
    float tot = 0.f;
    #pragma unroll
    for (int i = 0; i < 8; i++) tot += wred[i];
    float val = e / tot;
    p[t] = val;
    int b = (int)(row >> 8);
    atomicAdd(&g_colsum[b * CC + t], val);
}
__global__ void k_scaleAtt(){
    size_t i = ((size_t)blockIdx.x * blockDim.x + threadIdx.x) * 4;
    int b = (int)(i >> 16);
    int d = (int)(i & 255);
    float4 a  = *(const float4*)(g_att + i);
    float4 cs = *(const float4*)(g_colsum + b * CC + d);
    float v0 = a.x / (1e-9f + cs.x), v1 = a.y / (1e-9f + cs.y);
    float v2 = a.z / (1e-9f + cs.z), v3 = a.w / (1e-9f + cs.w);
    uint32_t h0,l0,h1,l1;
    split_pair(v0,v1,h0,l0); split_pair(v2,v3,h1,l1);
    *(uint2*)(g_atthi + i) = make_uint2(h0,h1);
    *(uint2*)(g_attlo + i) = make_uint2(l0,l1);
}

// ---------------- BN stats from G: per-channel scale/shift ------------------
__global__ void k_bnfin2(const float* __restrict__ gamma, const float* __restrict__ beta){
    int o = blockIdx.x, t = threadIdx.x, lane = t & 31, w = t >> 5;
    __shared__ float rq[8], rl[8];
    float sum_t = 0.f, sumsq = 0.f;
    for (int b = 0; b < BB; b++){
        size_t ro = (size_t)b * CC * CC + (size_t)o * CC;
        float F = __bfloat162float(g_Fhi[ro + t]) + __bfloat162float(g_Flo[ro + t]);
        float ql = g_att[ro + t] * F;
        float ll = g_sx[b * CC + t] * F;
        #pragma unroll
        for (int off = 16; off > 0; off >>= 1){
            ql += __shfl_xor_sync(0xffffffffu, ql, off);
            ll += __shfl_xor_sync(0xffffffffu, ll, off);
        }
        if (lane == 0){ rq[w] = ql; rl[w] = ll; }
        __syncthreads();
        if (t == 0){
            float q = 0.f, l = 0.f;
            #pragma unroll
            for (int i = 0; i < 8; i++){ q += rq[i]; l += rl[i]; }
            float be = g_beff[b * CC + o];
            sum_t += l + (float)NN * be;
            sumsq += q + 2.f * be * l + (float)NN * be * be;
        }
        __syncthreads();
    }
    if (t == 0){
        float inv = 1.0f / (float)(BB * NN);
        float mean = sum_t * inv;
        float var  = sumsq * inv - mean * mean;
        float rstd = rsqrtf(var + 1e-5f);
        float sc = gamma[o] * rstd;
        g_scale[o] = sc;
        g_shift[o] = beta[o] - mean * sc;
    }
}

// ---------------- KT7: out = x + relu(scale*(x.Weff^T + beff) + shift) ------
__global__ void __launch_bounds__(256, 2)
kt7(const float* __restrict__ x, float* __restrict__ out){
    extern __shared__ char smem[];
    int b = blockIdx.z;
    int mBase = blockIdx.x * 128;   // n
    int oBase = blockIdx.y * 64;    // o
    const bf16* Ah = g_xhi + ((size_t)b * NN + mBase) * CC;
    const bf16* Al = g_xlo + ((size_t)b * NN + mBase) * CC;
    const bf16* Bh = g_Fhi + ((size_t)b * CC + oBase) * CC;
    const bf16* Bl = g_Flo + ((size_t)b * CC + oBase) * CC;
    float acc[2][4][4] = {};
    gemm_main(smem, Ah, Al, CC, Bh, Bl, CC, 4, acc);

    int tid = threadIdx.x, lane = tid & 31, wid = tid >> 5;
    int warpM = wid & 3, warpN = wid >> 2;
    int gr = lane >> 2, gc = (lane & 3) * 2;
    #pragma unroll
    for (int nf = 0; nf < 4; nf++){
        int col = warpN * 32 + nf * 8 + gc;
        int o = oBase + col;
        float be0 = g_beff[b * CC + o], be1 = g_beff[b * CC + o + 1];
        float sc0 = g_scale[o], sc1 = g_scale[o + 1];
        float sh0 = g_shift[o], sh1 = g_shift[o + 1];
        #pragma unroll
        for (int mf = 0; mf < 2; mf++){
            float* c = acc[mf][nf];
            int row0 = warpM * 32 + mf * 16 + gr;
            #pragma unroll
            for (int h = 0; h < 2; h++){
                int n = mBase + row0 + h * 8;
                size_t di = ((size_t)b * NN + n) * CC + o;
                float t0 = c[2*h] + be0, t1 = c[2*h+1] + be1;
                float2 xv = *(const float2*)(x + di);
                float r0 = xv.x + fmaxf(fmaf(t0, sc0, sh0), 0.f);
                float r1 = xv.y + fmaxf(fmaf(t1, sc1, sh1), 0.f);
                *(float2*)(out + di) = make_float2(r0, r1);
            }
        }
    }
}

// ---------------- launch ----------------------------------------------------
extern "C" void kernel_launch(void* const* d_in, const int* in_sizes, int n_in,
                              void* d_out, int out_size){
    (void)in_sizes; (void)n_in; (void)out_size;
    const float* x     = (const float*)d_in[1];
    const float* Wq    = (const float*)d_in[2];
    const float* Wv    = (const float*)d_in[3];
    const float* bv    = (const float*)d_in[4];
    const float* Wt    = (const float*)d_in[5];
    const float* bt    = (const float*)d_in[6];
    const float* gamma = (const float*)d_in[7];
    const float* beta  = (const float*)d_in[8];
    float* out = (float*)d_out;

    static bool init_done = false;
    if (!init_done){
        cudaFuncSetAttribute(ktG, cudaFuncAttributeMaxDynamicSharedMemorySize, SDYN2);
        cudaFuncSetAttribute(ksq, cudaFuncAttributeMaxDynamicSharedMemorySize, SDYN64);
        cudaFuncSetAttribute(kt7, cudaFuncAttributeMaxDynamicSharedMemorySize, SDYN2);
        init_done = true;
    }

    k_cvt_w   <<<768, 256>>>(Wq, Wv, Wt);           // also zeros colsum, sx
    k_cvt_x   <<<dim3(64, 4, BB), 256>>>(x);
    ktG       <<<dim3(6, 1, 3*BB), 256, SDYN2>>>();
    k_gsum    <<<1024, 256>>>();
    ksq       <<<dim3(4, 4, BB), 256, SDYN64>>>(0, Wt, bt, bv);
    ksq       <<<dim3(4, 4, BB), 256, SDYN64>>>(1, Wt, bt, bv);
    k_softmax <<<BB*CC, 256>>>();
    k_scaleAtt<<<1024, 256>>>();
    ksq       <<<dim3(4, 4, BB), 256, SDYN64>>>(2, Wt, bt, bv);
    ksq       <<<dim3(4, 4, BB), 256, SDYN64>>>(3, Wt, bt, bv);
    ksq       <<<dim3(4, 4, BB), 256, SDYN64>>>(4, Wt, bt, bv);
    k_bnfin2  <<<CC, 256>>>(gamma, beta);
    kt7       <<<dim3(32, 4, BB), 256, SDYN2>>>(x, out);
}